// round 5
// baseline (speedup 1.0000x reference)
#include <cuda_runtime.h>
#include <cuda_fp16.h>
#include <cstdint>
#include <stdint.h>
#include <math.h>

// Problem constants
#define Bdim 2
#define Sdim 2048
#define Hdim 2048
#define NHdim 16
#define Ddim 128
#define FFdim 8192
#define Mrows (Bdim*Sdim)   // 4096

// -------- scratch (device globals; no allocation) --------
__device__ float g_qkv[(size_t)Mrows*3*Hdim];    // QKV gemm out (fp32, for rope)
__device__ float g_q[(size_t)Mrows*Hdim];        // [B,NH,S,D]
__device__ float g_k[(size_t)Mrows*Hdim];
__device__ float g_v[(size_t)Mrows*Hdim];
__device__ float g_hidden[(size_t)Mrows*Hdim];   // residual+attn_out
__device__ float g_cos[Sdim*64];
__device__ float g_sin[Sdim*64];
// fp16 hi/lo operand arrays
__device__ __half g_xh[(size_t)Mrows*Hdim],      g_xl[(size_t)Mrows*Hdim];
__device__ __half g_ctxh[(size_t)Mrows*Hdim],    g_ctxl[(size_t)Mrows*Hdim];
__device__ __half g_interh[(size_t)Mrows*FFdim], g_interl[(size_t)Mrows*FFdim];
__device__ __half g_wqkvh[(size_t)3*Hdim*Hdim],  g_wqkvl[(size_t)3*Hdim*Hdim];
__device__ __half g_wdh[(size_t)Hdim*Hdim],      g_wdl[(size_t)Hdim*Hdim];
__device__ __half g_w1h[(size_t)FFdim*Hdim],     g_w1l[(size_t)FFdim*Hdim];
__device__ __half g_w2h[(size_t)Hdim*FFdim],     g_w2l[(size_t)Hdim*FFdim];

// ============================ helpers ============================
__device__ __forceinline__ uint32_t smem_u32(const void* p) {
    uint32_t a;
    asm("{ .reg .u64 t; cvta.to.shared.u64 t, %1; cvt.u32.u64 %0, t; }" : "=r"(a) : "l"(p));
    return a;
}
__device__ __forceinline__ void ldsm4(uint32_t* r, uint32_t addr) {
    asm volatile("ldmatrix.sync.aligned.m8n8.x4.shared.b16 {%0,%1,%2,%3}, [%4];"
        : "=r"(r[0]), "=r"(r[1]), "=r"(r[2]), "=r"(r[3]) : "r"(addr));
}
__device__ __forceinline__ void mma16816(float* c, const uint32_t* a, uint32_t b0, uint32_t b1) {
    asm volatile("mma.sync.aligned.m16n8k16.row.col.f32.f16.f16.f32 "
        "{%0,%1,%2,%3}, {%4,%5,%6,%7}, {%8,%9}, {%0,%1,%2,%3};"
        : "+f"(c[0]), "+f"(c[1]), "+f"(c[2]), "+f"(c[3])
        : "r"(a[0]), "r"(a[1]), "r"(a[2]), "r"(a[3]), "r"(b0), "r"(b1));
}
__device__ __forceinline__ void cp16(uint32_t dst, const void* src) {
    asm volatile("cp.async.cg.shared.global [%0], [%1], 16;"
        :: "r"(dst), "l"(__cvta_generic_to_global(src)) : "memory");
}
#define CP_COMMIT() asm volatile("cp.async.commit_group;" ::: "memory")
#define CP_WAIT(n)  asm volatile("cp.async.wait_group %0;" :: "n"(n) : "memory")

// swizzled smem offset: rows of 64B (32 halfs), 16B chunk XOR (row>>1)&3
__device__ __forceinline__ uint32_t swoff(int row, int chunk) {
    return (uint32_t)(row * 64 + ((chunk ^ ((row >> 1) & 3)) << 4));
}
// split fp32 pair -> hi/lo half2
__device__ __forceinline__ void split2(float a, float b, __half2& h, __half2& l) {
    h = __floats2half2_rn(a, b);
    float2 hf = __half22float2(h);
    l = __floats2half2_rn(a - hf.x, b - hf.y);
}

// ============================ weight split kernel ============================
__global__ void split_kernel(const float* __restrict__ in, __half* __restrict__ hi,
                             __half* __restrict__ lo, int n2) {
    int i = blockIdx.x * blockDim.x + threadIdx.x;
    if (i >= n2) return;
    float2 v = *(const float2*)(in + (size_t)i * 2);
    __half2 h, l;
    split2(v.x, v.y, h, l);
    *(__half2*)(hi + (size_t)i * 2) = h;
    *(__half2*)(lo + (size_t)i * 2) = l;
}

// ============================ HMMA GEMM v2 (fp16 hi/lo pre-split, cp.async) ============================
// A: [M,K] half (Ah+Al), W: [N,K] half (Wh+Wl). 3-pass: AhWh + AhWl + AlWh.
// EPI: 0 = bias -> C fp32 ; 1 = bias+GELU -> Ch/Cl halves ; 2 = bias+residual -> C fp32
#define NSTAGE 4
#define STAGE_BYTES 32768
#define HM_SMEM (NSTAGE*STAGE_BYTES)

template<int EPI>
__global__ void __launch_bounds__(256, 1) hgemm(
    const __half* __restrict__ Ah, const __half* __restrict__ Al,
    const __half* __restrict__ Wh, const __half* __restrict__ Wl,
    const float* __restrict__ bias, const float* __restrict__ res,
    float* __restrict__ C, __half* __restrict__ Ch, __half* __restrict__ Cl,
    int M, int N, int K)
{
    extern __shared__ char sm[];
    uint32_t smb = smem_u32(sm);
    int tid = threadIdx.x;
    int lane = tid & 31, wid = tid >> 5;
    int wm = (wid & 3) * 32;
    int wn = (wid >> 2) * 64;
    int bm = blockIdx.y * 128, bn = blockIdx.x * 128;

    // loader coords: row tid/2, 16 halfs (2 chunks) at chunk pair (tid&1)*2
    int lrow = tid >> 1;
    int lcol = (tid & 1) * 16;
    int lco  = (tid & 1) * 2;
    const __half* pAh = Ah + (size_t)(bm + lrow) * K + lcol;
    const __half* pAl = Al + (size_t)(bm + lrow) * K + lcol;
    const __half* pWh = Wh + (size_t)(bn + lrow) * K + lcol;
    const __half* pWl = Wl + (size_t)(bn + lrow) * K + lcol;
    uint32_t d0 = swoff(lrow, lco), d1 = swoff(lrow, lco + 1);

    float acc[2][8][4];
#pragma unroll
    for (int i = 0; i < 2; i++)
#pragma unroll
        for (int j = 0; j < 8; j++)
#pragma unroll
            for (int q = 0; q < 4; q++) acc[i][j][q] = 0.f;

    int mat = lane >> 3, mr = lane & 7;
    int fr_row = (mat & 1) * 8 + mr;
    int fr_ch  = mat >> 1;

    const int NC = K >> 5;

    auto load_stage = [&](int c) {
        uint32_t base = smb + (uint32_t)(c & (NSTAGE - 1)) * STAGE_BYTES;
        size_t ko = (size_t)c * 32;
        cp16(base + 0     + d0, pAh + ko); cp16(base + 0     + d1, pAh + ko + 8);
        cp16(base + 8192  + d0, pAl + ko); cp16(base + 8192  + d1, pAl + ko + 8);
        cp16(base + 16384 + d0, pWh + ko); cp16(base + 16384 + d1, pWh + ko + 8);
        cp16(base + 24576 + d0, pWl + ko); cp16(base + 24576 + d1, pWl + ko + 8);
    };

    // prologue: 3 stages in flight
#pragma unroll
    for (int c = 0; c < NSTAGE - 1; c++) { load_stage(c); CP_COMMIT(); }

    for (int c = 0; c < NC; c++) {
        CP_WAIT(NSTAGE - 2);
        __syncthreads();

        // prefetch next stage (overwrites stage c-1, all warps already past it)
        if (c + NSTAGE - 1 < NC) { load_stage(c + NSTAGE - 1); }
        CP_COMMIT();

        uint32_t base = smb + (uint32_t)(c & (NSTAGE - 1)) * STAGE_BYTES;
#pragma unroll
        for (int kk = 0; kk < 2; kk++) {
            uint32_t ah[2][4], al[2][4];
            uint32_t bh[4][4], bl[4][4];
#pragma unroll
            for (int i = 0; i < 2; i++) {
                uint32_t off = swoff(wm + i * 16 + fr_row, kk * 2 + fr_ch);
                ldsm4(ah[i], base + 0    + off);
                ldsm4(al[i], base + 8192 + off);
            }
#pragma unroll
            for (int j = 0; j < 4; j++) {
                uint32_t off = swoff(wn + j * 16 + fr_row, kk * 2 + fr_ch);
                ldsm4(bh[j], base + 16384 + off);
                ldsm4(bl[j], base + 24576 + off);
            }
#pragma unroll
            for (int i = 0; i < 2; i++) {
#pragma unroll
                for (int jj = 0; jj < 8; jj++) {
                    int g = jj >> 1, h = jj & 1;
                    mma16816(acc[i][jj], ah[i], bh[g][h], bh[g][h+2]);
                    mma16816(acc[i][jj], ah[i], bl[g][h], bl[g][h+2]);
                    mma16816(acc[i][jj], al[i], bh[g][h], bh[g][h+2]);
                }
            }
        }
        __syncthreads();
    }

    // epilogue
    int tr = lane >> 2;
    int tc = (lane & 3) * 2;
#pragma unroll
    for (int i = 0; i < 2; i++) {
#pragma unroll
        for (int jj = 0; jj < 8; jj++) {
            int n0 = bn + wn + jj * 8 + tc;
            float b0 = bias[n0], b1 = bias[n0 + 1];
#pragma unroll
            for (int half = 0; half < 2; half++) {
                int m = bm + wm + i * 16 + tr + half * 8;
                size_t idx = (size_t)m * N + n0;
                float v0 = acc[i][jj][half * 2 + 0] + b0;
                float v1 = acc[i][jj][half * 2 + 1] + b1;
                if (EPI == 1) {
                    v0 = 0.5f * v0 * (1.0f + erff(v0 * 0.70710678118654752f));
                    v1 = 0.5f * v1 * (1.0f + erff(v1 * 0.70710678118654752f));
                    __half2 h, l;
                    split2(v0, v1, h, l);
                    *(__half2*)(Ch + idx) = h;
                    *(__half2*)(Cl + idx) = l;
                } else {
                    if (EPI == 2) { v0 += res[idx]; v1 += res[idx + 1]; }
                    *(float2*)(C + idx) = make_float2(v0, v1);
                }
            }
        }
    }
}

// ============================ LayerNorm -> fp16 hi/lo ============================
__global__ void ln_kernel(const float* __restrict__ in, const float* __restrict__ w,
                          const float* __restrict__ b,
                          __half* __restrict__ oh, __half* __restrict__ ol) {
    __shared__ float2 red[256];
    int row = blockIdx.x;
    const float* x = in + (size_t)row * Hdim;
    float s = 0.f, ss = 0.f;
    for (int i = threadIdx.x * 2; i < Hdim; i += 512) {
        float2 v = *(const float2*)(x + i);
        s += v.x + v.y;
        ss = fmaf(v.x, v.x, fmaf(v.y, v.y, ss));
    }
    red[threadIdx.x] = make_float2(s, ss);
    __syncthreads();
    for (int o = 128; o > 0; o >>= 1) {
        if (threadIdx.x < o) {
            float2 a = red[threadIdx.x], c = red[threadIdx.x + o];
            red[threadIdx.x] = make_float2(a.x + c.x, a.y + c.y);
        }
        __syncthreads();
    }
    float mean = red[0].x * (1.0f / Hdim);
    float var  = red[0].y * (1.0f / Hdim) - mean * mean;
    float rstd = rsqrtf(var + 1e-5f);
    for (int i = threadIdx.x * 2; i < Hdim; i += 512) {
        float2 v = *(const float2*)(x + i);
        float2 wv = *(const float2*)(w + i);
        float2 bv = *(const float2*)(b + i);
        float o0 = (v.x - mean) * rstd * wv.x + bv.x;
        float o1 = (v.y - mean) * rstd * wv.y + bv.y;
        __half2 h, l;
        split2(o0, o1, h, l);
        *(__half2*)(oh + (size_t)row * Hdim + i) = h;
        *(__half2*)(ol + (size_t)row * Hdim + i) = l;
    }
}

// ============================ RoPE table (double precision trig) ============================
__global__ void rope_table_kernel() {
    int idx = blockIdx.x * blockDim.x + threadIdx.x;
    if (idx >= Sdim * 64) return;
    int s = idx >> 6, i = idx & 63;
    double invf = exp(-(double)i * (9.210340371976184 / 64.0)); // ln(10000)/64
    double th = (double)s * invf;
    g_cos[idx] = (float)cos(th);
    g_sin[idx] = (float)sin(th);
}

// ============================ QKV split + RoPE ============================
__global__ void rope_kernel() {
    int row = blockIdx.x;      // b*S + s
    int h = blockIdx.y;
    int d = threadIdx.x;       // 0..127
    int s = row & (Sdim - 1);
    int b = row >> 11;
    const float* src = g_qkv + (size_t)row * (3 * Hdim) + h * (3 * Ddim);
    float q = src[d];
    float k = src[Ddim + d];
    float v = src[2 * Ddim + d];
    int di = d & 63;
    float cs = g_cos[s * 64 + di];
    float sn = g_sin[s * 64 + di];
    float qp, kp;
    if (d < 64) { qp = -src[d + 64];        kp = -src[Ddim + d + 64]; }
    else        { qp =  src[d - 64];        kp =  src[Ddim + d - 64]; }
    size_t oidx = ((size_t)(b * NHdim + h) * Sdim + s) * Ddim + d;
    g_q[oidx] = q * cs + qp * sn;
    g_k[oidx] = k * cs + kp * sn;
    g_v[oidx] = v;
}

// ============================ Flash attention (fp32, causal) ============================
#define ATT_BR 64
#define ATT_BC 32
#define ATT_PD 132
#define ATT_PS 36
#define ATTN_SMEM_BYTES ((ATT_BR*ATT_PD + 2*ATT_BC*ATT_PD + ATT_BR*ATT_PS + 3*ATT_BR) * 4)

__global__ void __launch_bounds__(256) attn_kernel() {
    extern __shared__ float smf[];
    float* Qs  = smf;
    float* Ks  = Qs + ATT_BR * ATT_PD;
    float* Vs  = Ks + ATT_BC * ATT_PD;
    float* Ss  = Vs + ATT_BC * ATT_PD;
    float* m_s = Ss + ATT_BR * ATT_PS;
    float* l_s = m_s + ATT_BR;
    float* sc_s = l_s + ATT_BR;

    int qt = gridDim.x - 1 - blockIdx.x;
    int bh = blockIdx.y;
    int tid = threadIdx.x;
    int ty = tid >> 4, tx = tid & 15;

    const float* Qg = g_q + ((size_t)bh * Sdim + (size_t)qt * ATT_BR) * Ddim;
    const float* Kg = g_k + (size_t)bh * Sdim * Ddim;
    const float* Vg = g_v + (size_t)bh * Sdim * Ddim;

    for (int i = tid * 4; i < ATT_BR * Ddim; i += 1024) {
        float4 v = *(const float4*)(Qg + i);
        int r = i >> 7, c = i & 127;
        float* q = Qs + r * ATT_PD + c;
        q[0] = v.x; q[1] = v.y; q[2] = v.z; q[3] = v.w;
    }
    if (tid < ATT_BR) { m_s[tid] = -INFINITY; l_s[tid] = 0.f; }

    float acc[4][8];
#pragma unroll
    for (int i = 0; i < 4; i++)
#pragma unroll
        for (int j = 0; j < 8; j++) acc[i][j] = 0.f;

    int nkt = 2 * qt + 2;
    for (int kt = 0; kt < nkt; kt++) {
        __syncthreads();
        const float* Kt = Kg + (size_t)kt * ATT_BC * Ddim;
        const float* Vt = Vg + (size_t)kt * ATT_BC * Ddim;
        for (int i = tid * 4; i < ATT_BC * Ddim; i += 1024) {
            float4 kv = *(const float4*)(Kt + i);
            float4 vv = *(const float4*)(Vt + i);
            int r = i >> 7, c = i & 127;
            float* kp = Ks + r * ATT_PD + c;
            kp[0] = kv.x; kp[1] = kv.y; kp[2] = kv.z; kp[3] = kv.w;
            float* vp = Vs + r * ATT_PD + c;
            vp[0] = vv.x; vp[1] = vv.y; vp[2] = vv.z; vp[3] = vv.w;
        }
        __syncthreads();

        float sa[4][2];
#pragma unroll
        for (int i = 0; i < 4; i++) { sa[i][0] = 0.f; sa[i][1] = 0.f; }
        const float* q0 = Qs + (ty * 4) * ATT_PD;
        const float* k0 = Ks + (tx * 2) * ATT_PD;
        for (int k = 0; k < Ddim; k += 4) {
            float4 b0 = *(const float4*)(k0 + k);
            float4 b1 = *(const float4*)(k0 + ATT_PD + k);
#pragma unroll
            for (int i = 0; i < 4; i++) {
                float4 a = *(const float4*)(q0 + i * ATT_PD + k);
                sa[i][0] += a.x * b0.x + a.y * b0.y + a.z * b0.z + a.w * b0.w;
                sa[i][1] += a.x * b1.x + a.y * b1.y + a.z * b1.z + a.w * b1.w;
            }
        }
        int qbase = qt * ATT_BR + ty * 4;
        int kbase = kt * ATT_BC + tx * 2;
#pragma unroll
        for (int i = 0; i < 4; i++) {
#pragma unroll
            for (int j = 0; j < 2; j++) {
                float v = sa[i][j] * 0.08838834764831845f;
                if (kbase + j > qbase + i) v = -1e30f;
                Ss[(ty * 4 + i) * ATT_PS + tx * 2 + j] = v;
            }
        }
        __syncthreads();

        if (tid < ATT_BR) {
            float mold = m_s[tid];
            float mnew = mold;
            float* srow = Ss + tid * ATT_PS;
#pragma unroll
            for (int c = 0; c < ATT_BC; c++) mnew = fmaxf(mnew, srow[c]);
            float lsum = 0.f;
#pragma unroll
            for (int c = 0; c < ATT_BC; c++) {
                float p = expf(srow[c] - mnew);
                srow[c] = p;
                lsum += p;
            }
            float scl = expf(mold - mnew);
            sc_s[tid] = scl;
            l_s[tid] = l_s[tid] * scl + lsum;
            m_s[tid] = mnew;
        }
        __syncthreads();

#pragma unroll
        for (int i = 0; i < 4; i++) {
            float scl = sc_s[ty * 4 + i];
#pragma unroll
            for (int j = 0; j < 8; j++) acc[i][j] *= scl;
        }
        const float* s0 = Ss + (ty * 4) * ATT_PS;
        const float* v0 = Vs + tx * 8;
        for (int c = 0; c < ATT_BC; c += 4) {
            float pr[4][4];
            *(float4*)pr[0] = *(const float4*)(s0 + 0 * ATT_PS + c);
            *(float4*)pr[1] = *(const float4*)(s0 + 1 * ATT_PS + c);
            *(float4*)pr[2] = *(const float4*)(s0 + 2 * ATT_PS + c);
            *(float4*)pr[3] = *(const float4*)(s0 + 3 * ATT_PS + c);
#pragma unroll
            for (int cc = 0; cc < 4; cc++) {
                float4 va = *(const float4*)(v0 + (c + cc) * ATT_PD);
                float4 vb = *(const float4*)(v0 + (c + cc) * ATT_PD + 4);
#pragma unroll
                for (int i = 0; i < 4; i++) {
                    float p = pr[i][cc];
                    acc[i][0] = fmaf(p, va.x, acc[i][0]);
                    acc[i][1] = fmaf(p, va.y, acc[i][1]);
                    acc[i][2] = fmaf(p, va.z, acc[i][2]);
                    acc[i][3] = fmaf(p, va.w, acc[i][3]);
                    acc[i][4] = fmaf(p, vb.x, acc[i][4]);
                    acc[i][5] = fmaf(p, vb.y, acc[i][5]);
                    acc[i][6] = fmaf(p, vb.z, acc[i][6]);
                    acc[i][7] = fmaf(p, vb.w, acc[i][7]);
                }
            }
        }
    }

    // write ctx as fp16 hi/lo in [B,S,H]
    int b = bh >> 4, h = bh & 15;
#pragma unroll
    for (int i = 0; i < 4; i++) {
        int r = ty * 4 + i;
        int sg = qt * ATT_BR + r;
        float inv = 1.0f / l_s[r];
        size_t off = ((size_t)(b * Sdim + sg) * Hdim) + h * Ddim + tx * 8;
#pragma unroll
        for (int j = 0; j < 8; j += 2) {
            float a0 = acc[i][j] * inv, a1 = acc[i][j + 1] * inv;
            __half2 hh, ll;
            split2(a0, a1, hh, ll);
            *(__half2*)(g_ctxh + off + j) = hh;
            *(__half2*)(g_ctxl + off + j) = ll;
        }
    }
}

// ============================ mask passthrough ============================
__global__ void mask_kernel(const unsigned char* __restrict__ m, float* __restrict__ o, int n) {
    int i = blockIdx.x * blockDim.x + threadIdx.x;
    if (i < n) o[i] = m[i] ? 1.0f : 0.0f;
}

// ============================ launch ============================
extern "C" void kernel_launch(void* const* d_in, const int* in_sizes, int n_in,
                              void* d_out, int out_size) {
    const float* hs            = (const float*)d_in[0];
    const unsigned char* mask  = (const unsigned char*)d_in[1];
    const float* ln1w          = (const float*)d_in[2];
    const float* ln1b          = (const float*)d_in[3];
    const float* wqkv          = (const float*)d_in[4];
    const float* bqkv          = (const float*)d_in[5];
    const float* wdense        = (const float*)d_in[6];
    const float* bdense        = (const float*)d_in[7];
    const float* ln2w          = (const float*)d_in[8];
    const float* ln2b          = (const float*)d_in[9];
    const float* w1            = (const float*)d_in[10];
    const float* b1            = (const float*)d_in[11];
    const float* w2            = (const float*)d_in[12];
    const float* b2            = (const float*)d_in[13];
    float* out = (float*)d_out;

    float *pqkv, *phid;
    __half *pxh, *pxl, *pctxh, *pctxl, *pinterh, *pinterl;
    __half *pwqkvh, *pwqkvl, *pwdh, *pwdl, *pw1h, *pw1l, *pw2h, *pw2l;
    cudaGetSymbolAddress((void**)&pqkv,   g_qkv);
    cudaGetSymbolAddress((void**)&phid,   g_hidden);
    cudaGetSymbolAddress((void**)&pxh,    g_xh);
    cudaGetSymbolAddress((void**)&pxl,    g_xl);
    cudaGetSymbolAddress((void**)&pctxh,  g_ctxh);
    cudaGetSymbolAddress((void**)&pctxl,  g_ctxl);
    cudaGetSymbolAddress((void**)&pinterh, g_interh);
    cudaGetSymbolAddress((void**)&pinterl, g_interl);
    cudaGetSymbolAddress((void**)&pwqkvh, g_wqkvh);
    cudaGetSymbolAddress((void**)&pwqkvl, g_wqkvl);
    cudaGetSymbolAddress((void**)&pwdh,   g_wdh);
    cudaGetSymbolAddress((void**)&pwdl,   g_wdl);
    cudaGetSymbolAddress((void**)&pw1h,   g_w1h);
    cudaGetSymbolAddress((void**)&pw1l,   g_w1l);
    cudaGetSymbolAddress((void**)&pw2h,   g_w2h);
    cudaGetSymbolAddress((void**)&pw2l,   g_w2l);

    cudaFuncSetAttribute(attn_kernel, cudaFuncAttributeMaxDynamicSharedMemorySize,
                         ATTN_SMEM_BYTES);
    cudaFuncSetAttribute(hgemm<0>, cudaFuncAttributeMaxDynamicSharedMemorySize, HM_SMEM);
    cudaFuncSetAttribute(hgemm<1>, cudaFuncAttributeMaxDynamicSharedMemorySize, HM_SMEM);
    cudaFuncSetAttribute(hgemm<2>, cudaFuncAttributeMaxDynamicSharedMemorySize, HM_SMEM);

    // weight splits (fp32 -> fp16 hi/lo)
    split_kernel<<<(3*Hdim*Hdim/2 + 255)/256, 256>>>(wqkv,   pwqkvh, pwqkvl, 3*Hdim*Hdim/2);
    split_kernel<<<(Hdim*Hdim/2   + 255)/256, 256>>>(wdense, pwdh,   pwdl,   Hdim*Hdim/2);
    split_kernel<<<(FFdim*Hdim/2  + 255)/256, 256>>>(w1,     pw1h,   pw1l,   FFdim*Hdim/2);
    split_kernel<<<(Hdim*FFdim/2  + 255)/256, 256>>>(w2,     pw2h,   pw2l,   Hdim*FFdim/2);
    // LN1 -> xh/xl
    ln_kernel<<<Mrows, 256>>>(hs, ln1w, ln1b, pxh, pxl);
    // RoPE trig table
    rope_table_kernel<<<(Sdim * 64) / 256, 256>>>();
    // QKV = x @ wqkv^T + bqkv (fp32 out for rope)
    hgemm<0><<<dim3(3 * Hdim / 128, Mrows / 128), 256, HM_SMEM>>>(
        pxh, pxl, pwqkvh, pwqkvl, bqkv, nullptr, pqkv, nullptr, nullptr,
        Mrows, 3 * Hdim, Hdim);
    // split + rope -> g_q, g_k, g_v in [B,NH,S,D]
    rope_kernel<<<dim3(Mrows, NHdim), 128>>>();
    // flash attention -> ctxh/ctxl in [B,S,H]
    attn_kernel<<<dim3(Sdim / ATT_BR, Bdim * NHdim), 256, ATTN_SMEM_BYTES>>>();
    // dense + residual(hidden_states) -> g_hidden (fp32)
    hgemm<2><<<dim3(Hdim / 128, Mrows / 128), 256, HM_SMEM>>>(
        pctxh, pctxl, pwdh, pwdl, bdense, hs, phid, nullptr, nullptr,
        Mrows, Hdim, Hdim);
    // LN2 -> xh/xl
    ln_kernel<<<Mrows, 256>>>(phid, ln2w, ln2b, pxh, pxl);
    // FF1 + GELU -> interh/interl (fp16 hi/lo)
    hgemm<1><<<dim3(FFdim / 128, Mrows / 128), 256, HM_SMEM>>>(
        pxh, pxl, pw1h, pw1l, b1, nullptr, nullptr, pinterh, pinterl,
        Mrows, FFdim, Hdim);
    // FF2 + residual(g_hidden) -> out
    hgemm<2><<<dim3(Hdim / 128, Mrows / 128), 256, HM_SMEM>>>(
        pinterh, pinterl, pw2h, pw2l, b2, phid, out, nullptr, nullptr,
        Mrows, Hdim, FFdim);
    // if output also carries the attention mask, convert it after hidden
    long long hid_elems = (long long)Mrows * Hdim;           // 8388608
    long long mask_elems = (long long)Sdim * Sdim;           // 4194304
    if ((long long)out_size >= hid_elems + mask_elems) {
        mask_kernel<<<(int)(mask_elems / 256), 256>>>(mask, out + hid_elems, (int)mask_elems);
    }
}

// round 6
// speedup vs baseline: 1.0311x; 1.0311x over previous
#include <cuda_runtime.h>
#include <cuda_fp16.h>
#include <cstdint>
#include <stdint.h>
#include <math.h>

// Problem constants
#define Bdim 2
#define Sdim 2048
#define Hdim 2048
#define NHdim 16
#define Ddim 128
#define FFdim 8192
#define Mrows (Bdim*Sdim)   // 4096

// -------- scratch (device globals; no allocation) --------
__device__ float g_qkv[(size_t)Mrows*3*Hdim];    // QKV gemm out (fp32, for rope)
__device__ float g_q[(size_t)Mrows*Hdim];        // [B,NH,S,D]
__device__ float g_k[(size_t)Mrows*Hdim];
__device__ float g_v[(size_t)Mrows*Hdim];
__device__ float g_hidden[(size_t)Mrows*Hdim];   // residual+attn_out
__device__ float g_cos[Sdim*64];
__device__ float g_sin[Sdim*64];
// fp16 hi/lo operand arrays
__device__ __half g_xh[(size_t)Mrows*Hdim],      g_xl[(size_t)Mrows*Hdim];
__device__ __half g_ctxh[(size_t)Mrows*Hdim],    g_ctxl[(size_t)Mrows*Hdim];
__device__ __half g_interh[(size_t)Mrows*FFdim], g_interl[(size_t)Mrows*FFdim];
__device__ __half g_wqkvh[(size_t)3*Hdim*Hdim],  g_wqkvl[(size_t)3*Hdim*Hdim];
__device__ __half g_wdh[(size_t)Hdim*Hdim],      g_wdl[(size_t)Hdim*Hdim];
__device__ __half g_w1h[(size_t)FFdim*Hdim],     g_w1l[(size_t)FFdim*Hdim];
__device__ __half g_w2h[(size_t)Hdim*FFdim],     g_w2l[(size_t)Hdim*FFdim];

// ============================ helpers ============================
__device__ __forceinline__ uint32_t smem_u32(const void* p) {
    uint32_t a;
    asm("{ .reg .u64 t; cvta.to.shared.u64 t, %1; cvt.u32.u64 %0, t; }" : "=r"(a) : "l"(p));
    return a;
}
__device__ __forceinline__ void ldsm4(uint32_t* r, uint32_t addr) {
    asm volatile("ldmatrix.sync.aligned.m8n8.x4.shared.b16 {%0,%1,%2,%3}, [%4];"
        : "=r"(r[0]), "=r"(r[1]), "=r"(r[2]), "=r"(r[3]) : "r"(addr));
}
__device__ __forceinline__ void mma16816(float* c, const uint32_t* a, uint32_t b0, uint32_t b1) {
    asm volatile("mma.sync.aligned.m16n8k16.row.col.f32.f16.f16.f32 "
        "{%0,%1,%2,%3}, {%4,%5,%6,%7}, {%8,%9}, {%0,%1,%2,%3};"
        : "+f"(c[0]), "+f"(c[1]), "+f"(c[2]), "+f"(c[3])
        : "r"(a[0]), "r"(a[1]), "r"(a[2]), "r"(a[3]), "r"(b0), "r"(b1));
}
__device__ __forceinline__ void cp16(uint32_t dst, const void* src) {
    asm volatile("cp.async.cg.shared.global [%0], [%1], 16;"
        :: "r"(dst), "l"(__cvta_generic_to_global(src)) : "memory");
}
#define CP_COMMIT() asm volatile("cp.async.commit_group;" ::: "memory")
#define CP_WAIT(n)  asm volatile("cp.async.wait_group %0;" :: "n"(n) : "memory")

// swizzled smem offset: rows of 64B (32 halfs), 16B chunk XOR (row>>1)&3
__device__ __forceinline__ uint32_t swoff(int row, int chunk) {
    return (uint32_t)(row * 64 + ((chunk ^ ((row >> 1) & 3)) << 4));
}
// split fp32 pair -> hi/lo half2
__device__ __forceinline__ void split2(float a, float b, __half2& h, __half2& l) {
    h = __floats2half2_rn(a, b);
    float2 hf = __half22float2(h);
    l = __floats2half2_rn(a - hf.x, b - hf.y);
}

// ============================ weight split kernel ============================
__global__ void split_kernel(const float* __restrict__ in, __half* __restrict__ hi,
                             __half* __restrict__ lo, int n2) {
    int i = blockIdx.x * blockDim.x + threadIdx.x;
    if (i >= n2) return;
    float2 v = *(const float2*)(in + (size_t)i * 2);
    __half2 h, l;
    split2(v.x, v.y, h, l);
    *(__half2*)(hi + (size_t)i * 2) = h;
    *(__half2*)(lo + (size_t)i * 2) = l;
}

// ============================ HMMA GEMM v3 (256x128 tile, 512 thr, 3-stage cp.async) ============================
// A: [M,K] half (Ah+Al), W: [N,K] half (Wh+Wl). 3-pass: AhWh + AhWl + AlWh.
// EPI: 0 = bias -> C fp32 ; 1 = bias+GELU -> Ch/Cl halves ; 2 = bias+residual -> C fp32
#define GBM 256
#define GBN 128
#define NSTAGE 3
#define STAGE_BYTES 49152     // Ah 16K | Al 16K | Wh 8K | Wl 8K
#define HM_SMEM (NSTAGE*STAGE_BYTES)

template<int EPI>
__global__ void __launch_bounds__(512, 1) hgemm(
    const __half* __restrict__ Ah_, const __half* __restrict__ Al_,
    const __half* __restrict__ Wh_, const __half* __restrict__ Wl_,
    const float* __restrict__ bias, const float* __restrict__ res,
    float* __restrict__ C, __half* __restrict__ Ch, __half* __restrict__ Cl,
    int M, int N, int K)
{
    extern __shared__ char sm[];
    uint32_t smb = smem_u32(sm);
    int tid = threadIdx.x;
    int lane = tid & 31, wid = tid >> 5;
    int wm = (wid & 3) * 64;       // 4 warp-rows over 256
    int wn = (wid >> 2) * 32;      // 4 warp-cols over 128
    int bm = blockIdx.y * GBM, bn = blockIdx.x * GBN;

    // loader coords: A -> 1024 chunk-slots (256 rows x 4 chunks), 2 per thread (same row)
    int aidx = tid * 2;
    int arow = aidx >> 2, ach = aidx & 3;
    // W -> 512 chunk-slots (128 rows x 4 chunks), 1 per thread
    int wrow = tid >> 2, wch = tid & 3;
    const __half* pAh = Ah_ + (size_t)(bm + arow) * K + ach * 8;
    const __half* pAl = Al_ + (size_t)(bm + arow) * K + ach * 8;
    const __half* pWh = Wh_ + (size_t)(bn + wrow) * K + wch * 8;
    const __half* pWl = Wl_ + (size_t)(bn + wrow) * K + wch * 8;
    uint32_t dA0 = swoff(arow, ach), dA1 = swoff(arow, ach + 1);
    uint32_t dW  = swoff(wrow, wch);

    float acc[4][4][4];
#pragma unroll
    for (int i = 0; i < 4; i++)
#pragma unroll
        for (int j = 0; j < 4; j++)
#pragma unroll
            for (int q = 0; q < 4; q++) acc[i][j][q] = 0.f;

    int mat = lane >> 3, mr = lane & 7;
    int fr_row = (mat & 1) * 8 + mr;
    int fr_ch  = mat >> 1;

    const int NC = K >> 5;

    auto load_stage = [&](int c) {
        uint32_t base = smb + (uint32_t)(c % NSTAGE) * STAGE_BYTES;
        size_t ko = (size_t)c * 32;
        cp16(base + 0     + dA0, pAh + ko);
        cp16(base + 0     + dA1, pAh + ko + 8);
        cp16(base + 16384 + dA0, pAl + ko);
        cp16(base + 16384 + dA1, pAl + ko + 8);
        cp16(base + 32768 + dW,  pWh + ko);
        cp16(base + 40960 + dW,  pWl + ko);
    };

    // prologue: 2 stages in flight
#pragma unroll
    for (int c = 0; c < NSTAGE - 1; c++) { load_stage(c); CP_COMMIT(); }

    for (int c = 0; c < NC; c++) {
        CP_WAIT(NSTAGE - 2);
        __syncthreads();
        if (c + NSTAGE - 1 < NC) { load_stage(c + NSTAGE - 1); }
        CP_COMMIT();

        uint32_t base = smb + (uint32_t)(c % NSTAGE) * STAGE_BYTES;
#pragma unroll
        for (int kk = 0; kk < 2; kk++) {
            uint32_t ah[4][4], al[4][4], bh[2][4];
#pragma unroll
            for (int i = 0; i < 4; i++) {
                uint32_t off = swoff(wm + i * 16 + fr_row, kk * 2 + fr_ch);
                ldsm4(ah[i], base + 0     + off);
                ldsm4(al[i], base + 16384 + off);
            }
#pragma unroll
            for (int g = 0; g < 2; g++) {
                uint32_t off = swoff(wn + g * 16 + fr_row, kk * 2 + fr_ch);
                ldsm4(bh[g], base + 32768 + off);
            }
            // passes 1 & 3 (share bh): ah*bh + al*bh
#pragma unroll
            for (int i = 0; i < 4; i++) {
#pragma unroll
                for (int jj = 0; jj < 4; jj++) {
                    int g = jj >> 1, h = jj & 1;
                    mma16816(acc[i][jj], ah[i], bh[g][h], bh[g][h+2]);
                    mma16816(acc[i][jj], al[i], bh[g][h], bh[g][h+2]);
                }
            }
            // pass 2: ah*bl (bl loaded late; al registers dead)
            uint32_t bl[2][4];
#pragma unroll
            for (int g = 0; g < 2; g++) {
                uint32_t off = swoff(wn + g * 16 + fr_row, kk * 2 + fr_ch);
                ldsm4(bl[g], base + 40960 + off);
            }
#pragma unroll
            for (int i = 0; i < 4; i++) {
#pragma unroll
                for (int jj = 0; jj < 4; jj++) {
                    int g = jj >> 1, h = jj & 1;
                    mma16816(acc[i][jj], ah[i], bl[g][h], bl[g][h+2]);
                }
            }
        }
    }

    // epilogue
    int tr = lane >> 2;
    int tc = (lane & 3) * 2;
#pragma unroll
    for (int i = 0; i < 4; i++) {
#pragma unroll
        for (int jj = 0; jj < 4; jj++) {
            int n0 = bn + wn + jj * 8 + tc;
            float b0 = bias[n0], b1 = bias[n0 + 1];
#pragma unroll
            for (int half = 0; half < 2; half++) {
                int m = bm + wm + i * 16 + tr + half * 8;
                size_t idx = (size_t)m * N + n0;
                float v0 = acc[i][jj][half * 2 + 0] + b0;
                float v1 = acc[i][jj][half * 2 + 1] + b1;
                if (EPI == 1) {
                    v0 = 0.5f * v0 * (1.0f + erff(v0 * 0.70710678118654752f));
                    v1 = 0.5f * v1 * (1.0f + erff(v1 * 0.70710678118654752f));
                    __half2 h, l;
                    split2(v0, v1, h, l);
                    *(__half2*)(Ch + idx) = h;
                    *(__half2*)(Cl + idx) = l;
                } else {
                    if (EPI == 2) { v0 += res[idx]; v1 += res[idx + 1]; }
                    *(float2*)(C + idx) = make_float2(v0, v1);
                }
            }
        }
    }
}

// ============================ LayerNorm -> fp16 hi/lo ============================
__global__ void ln_kernel(const float* __restrict__ in, const float* __restrict__ w,
                          const float* __restrict__ b,
                          __half* __restrict__ oh, __half* __restrict__ ol) {
    __shared__ float2 red[256];
    int row = blockIdx.x;
    const float* x = in + (size_t)row * Hdim;
    float s = 0.f, ss = 0.f;
    for (int i = threadIdx.x * 2; i < Hdim; i += 512) {
        float2 v = *(const float2*)(x + i);
        s += v.x + v.y;
        ss = fmaf(v.x, v.x, fmaf(v.y, v.y, ss));
    }
    red[threadIdx.x] = make_float2(s, ss);
    __syncthreads();
    for (int o = 128; o > 0; o >>= 1) {
        if (threadIdx.x < o) {
            float2 a = red[threadIdx.x], c = red[threadIdx.x + o];
            red[threadIdx.x] = make_float2(a.x + c.x, a.y + c.y);
        }
        __syncthreads();
    }
    float mean = red[0].x * (1.0f / Hdim);
    float var  = red[0].y * (1.0f / Hdim) - mean * mean;
    float rstd = rsqrtf(var + 1e-5f);
    for (int i = threadIdx.x * 2; i < Hdim; i += 512) {
        float2 v = *(const float2*)(x + i);
        float2 wv = *(const float2*)(w + i);
        float2 bv = *(const float2*)(b + i);
        float o0 = (v.x - mean) * rstd * wv.x + bv.x;
        float o1 = (v.y - mean) * rstd * wv.y + bv.y;
        __half2 h, l;
        split2(o0, o1, h, l);
        *(__half2*)(oh + (size_t)row * Hdim + i) = h;
        *(__half2*)(ol + (size_t)row * Hdim + i) = l;
    }
}

// ============================ RoPE table (double precision trig) ============================
__global__ void rope_table_kernel() {
    int idx = blockIdx.x * blockDim.x + threadIdx.x;
    if (idx >= Sdim * 64) return;
    int s = idx >> 6, i = idx & 63;
    double invf = exp(-(double)i * (9.210340371976184 / 64.0)); // ln(10000)/64
    double th = (double)s * invf;
    g_cos[idx] = (float)cos(th);
    g_sin[idx] = (float)sin(th);
}

// ============================ QKV split + RoPE ============================
__global__ void rope_kernel() {
    int row = blockIdx.x;      // b*S + s
    int h = blockIdx.y;
    int d = threadIdx.x;       // 0..127
    int s = row & (Sdim - 1);
    int b = row >> 11;
    const float* src = g_qkv + (size_t)row * (3 * Hdim) + h * (3 * Ddim);
    float q = src[d];
    float k = src[Ddim + d];
    float v = src[2 * Ddim + d];
    int di = d & 63;
    float cs = g_cos[s * 64 + di];
    float sn = g_sin[s * 64 + di];
    float qp, kp;
    if (d < 64) { qp = -src[d + 64];        kp = -src[Ddim + d + 64]; }
    else        { qp =  src[d - 64];        kp =  src[Ddim + d - 64]; }
    size_t oidx = ((size_t)(b * NHdim + h) * Sdim + s) * Ddim + d;
    g_q[oidx] = q * cs + qp * sn;
    g_k[oidx] = k * cs + kp * sn;
    g_v[oidx] = v;
}

// ============================ Flash attention (fp32, causal) ============================
#define ATT_BR 64
#define ATT_BC 32
#define ATT_PD 132
#define ATT_PS 36
#define ATTN_SMEM_BYTES ((ATT_BR*ATT_PD + 2*ATT_BC*ATT_PD + ATT_BR*ATT_PS + 3*ATT_BR) * 4)

__global__ void __launch_bounds__(256) attn_kernel() {
    extern __shared__ float smf[];
    float* Qs  = smf;
    float* Ks  = Qs + ATT_BR * ATT_PD;
    float* Vs  = Ks + ATT_BC * ATT_PD;
    float* Ss  = Vs + ATT_BC * ATT_PD;
    float* m_s = Ss + ATT_BR * ATT_PS;
    float* l_s = m_s + ATT_BR;
    float* sc_s = l_s + ATT_BR;

    int qt = gridDim.x - 1 - blockIdx.x;
    int bh = blockIdx.y;
    int tid = threadIdx.x;
    int ty = tid >> 4, tx = tid & 15;

    const float* Qg = g_q + ((size_t)bh * Sdim + (size_t)qt * ATT_BR) * Ddim;
    const float* Kg = g_k + (size_t)bh * Sdim * Ddim;
    const float* Vg = g_v + (size_t)bh * Sdim * Ddim;

    for (int i = tid * 4; i < ATT_BR * Ddim; i += 1024) {
        float4 v = *(const float4*)(Qg + i);
        int r = i >> 7, c = i & 127;
        float* q = Qs + r * ATT_PD + c;
        q[0] = v.x; q[1] = v.y; q[2] = v.z; q[3] = v.w;
    }
    if (tid < ATT_BR) { m_s[tid] = -INFINITY; l_s[tid] = 0.f; }

    float acc[4][8];
#pragma unroll
    for (int i = 0; i < 4; i++)
#pragma unroll
        for (int j = 0; j < 8; j++) acc[i][j] = 0.f;

    int nkt = 2 * qt + 2;
    for (int kt = 0; kt < nkt; kt++) {
        __syncthreads();
        const float* Kt = Kg + (size_t)kt * ATT_BC * Ddim;
        const float* Vt = Vg + (size_t)kt * ATT_BC * Ddim;
        for (int i = tid * 4; i < ATT_BC * Ddim; i += 1024) {
            float4 kv = *(const float4*)(Kt + i);
            float4 vv = *(const float4*)(Vt + i);
            int r = i >> 7, c = i & 127;
            float* kp = Ks + r * ATT_PD + c;
            kp[0] = kv.x; kp[1] = kv.y; kp[2] = kv.z; kp[3] = kv.w;
            float* vp = Vs + r * ATT_PD + c;
            vp[0] = vv.x; vp[1] = vv.y; vp[2] = vv.z; vp[3] = vv.w;
        }
        __syncthreads();

        float sa[4][2];
#pragma unroll
        for (int i = 0; i < 4; i++) { sa[i][0] = 0.f; sa[i][1] = 0.f; }
        const float* q0 = Qs + (ty * 4) * ATT_PD;
        const float* k0 = Ks + (tx * 2) * ATT_PD;
        for (int k = 0; k < Ddim; k += 4) {
            float4 b0 = *(const float4*)(k0 + k);
            float4 b1 = *(const float4*)(k0 + ATT_PD + k);
#pragma unroll
            for (int i = 0; i < 4; i++) {
                float4 a = *(const float4*)(q0 + i * ATT_PD + k);
                sa[i][0] += a.x * b0.x + a.y * b0.y + a.z * b0.z + a.w * b0.w;
                sa[i][1] += a.x * b1.x + a.y * b1.y + a.z * b1.z + a.w * b1.w;
            }
        }
        int qbase = qt * ATT_BR + ty * 4;
        int kbase = kt * ATT_BC + tx * 2;
#pragma unroll
        for (int i = 0; i < 4; i++) {
#pragma unroll
            for (int j = 0; j < 2; j++) {
                float v = sa[i][j] * 0.08838834764831845f;
                if (kbase + j > qbase + i) v = -1e30f;
                Ss[(ty * 4 + i) * ATT_PS + tx * 2 + j] = v;
            }
        }
        __syncthreads();

        if (tid < ATT_BR) {
            float mold = m_s[tid];
            float mnew = mold;
            float* srow = Ss + tid * ATT_PS;
#pragma unroll
            for (int c = 0; c < ATT_BC; c++) mnew = fmaxf(mnew, srow[c]);
            float lsum = 0.f;
#pragma unroll
            for (int c = 0; c < ATT_BC; c++) {
                float p = expf(srow[c] - mnew);
                srow[c] = p;
                lsum += p;
            }
            float scl = expf(mold - mnew);
            sc_s[tid] = scl;
            l_s[tid] = l_s[tid] * scl + lsum;
            m_s[tid] = mnew;
        }
        __syncthreads();

#pragma unroll
        for (int i = 0; i < 4; i++) {
            float scl = sc_s[ty * 4 + i];
#pragma unroll
            for (int j = 0; j < 8; j++) acc[i][j] *= scl;
        }
        const float* s0 = Ss + (ty * 4) * ATT_PS;
        const float* v0 = Vs + tx * 8;
        for (int c = 0; c < ATT_BC; c += 4) {
            float pr[4][4];
            *(float4*)pr[0] = *(const float4*)(s0 + 0 * ATT_PS + c);
            *(float4*)pr[1] = *(const float4*)(s0 + 1 * ATT_PS + c);
            *(float4*)pr[2] = *(const float4*)(s0 + 2 * ATT_PS + c);
            *(float4*)pr[3] = *(const float4*)(s0 + 3 * ATT_PS + c);
#pragma unroll
            for (int cc = 0; cc < 4; cc++) {
                float4 va = *(const float4*)(v0 + (c + cc) * ATT_PD);
                float4 vb = *(const float4*)(v0 + (c + cc) * ATT_PD + 4);
#pragma unroll
                for (int i = 0; i < 4; i++) {
                    float p = pr[i][cc];
                    acc[i][0] = fmaf(p, va.x, acc[i][0]);
                    acc[i][1] = fmaf(p, va.y, acc[i][1]);
                    acc[i][2] = fmaf(p, va.z, acc[i][2]);
                    acc[i][3] = fmaf(p, va.w, acc[i][3]);
                    acc[i][4] = fmaf(p, vb.x, acc[i][4]);
                    acc[i][5] = fmaf(p, vb.y, acc[i][5]);
                    acc[i][6] = fmaf(p, vb.z, acc[i][6]);
                    acc[i][7] = fmaf(p, vb.w, acc[i][7]);
                }
            }
        }
    }

    // write ctx as fp16 hi/lo in [B,S,H]
    int b = bh >> 4, h = bh & 15;
#pragma unroll
    for (int i = 0; i < 4; i++) {
        int r = ty * 4 + i;
        int sg = qt * ATT_BR + r;
        float inv = 1.0f / l_s[r];
        size_t off = ((size_t)(b * Sdim + sg) * Hdim) + h * Ddim + tx * 8;
#pragma unroll
        for (int j = 0; j < 8; j += 2) {
            float a0 = acc[i][j] * inv, a1 = acc[i][j + 1] * inv;
            __half2 hh, ll;
            split2(a0, a1, hh, ll);
            *(__half2*)(g_ctxh + off + j) = hh;
            *(__half2*)(g_ctxl + off + j) = ll;
        }
    }
}

// ============================ mask passthrough ============================
__global__ void mask_kernel(const unsigned char* __restrict__ m, float* __restrict__ o, int n) {
    int i = blockIdx.x * blockDim.x + threadIdx.x;
    if (i < n) o[i] = m[i] ? 1.0f : 0.0f;
}

// ============================ launch ============================
extern "C" void kernel_launch(void* const* d_in, const int* in_sizes, int n_in,
                              void* d_out, int out_size) {
    const float* hs            = (const float*)d_in[0];
    const unsigned char* mask  = (const unsigned char*)d_in[1];
    const float* ln1w          = (const float*)d_in[2];
    const float* ln1b          = (const float*)d_in[3];
    const float* wqkv          = (const float*)d_in[4];
    const float* bqkv          = (const float*)d_in[5];
    const float* wdense        = (const float*)d_in[6];
    const float* bdense        = (const float*)d_in[7];
    const float* ln2w          = (const float*)d_in[8];
    const float* ln2b          = (const float*)d_in[9];
    const float* w1            = (const float*)d_in[10];
    const float* b1            = (const float*)d_in[11];
    const float* w2            = (const float*)d_in[12];
    const float* b2            = (const float*)d_in[13];
    float* out = (float*)d_out;

    float *pqkv, *phid;
    __half *pxh, *pxl, *pctxh, *pctxl, *pinterh, *pinterl;
    __half *pwqkvh, *pwqkvl, *pwdh, *pwdl, *pw1h, *pw1l, *pw2h, *pw2l;
    cudaGetSymbolAddress((void**)&pqkv,   g_qkv);
    cudaGetSymbolAddress((void**)&phid,   g_hidden);
    cudaGetSymbolAddress((void**)&pxh,    g_xh);
    cudaGetSymbolAddress((void**)&pxl,    g_xl);
    cudaGetSymbolAddress((void**)&pctxh,  g_ctxh);
    cudaGetSymbolAddress((void**)&pctxl,  g_ctxl);
    cudaGetSymbolAddress((void**)&pinterh, g_interh);
    cudaGetSymbolAddress((void**)&pinterl, g_interl);
    cudaGetSymbolAddress((void**)&pwqkvh, g_wqkvh);
    cudaGetSymbolAddress((void**)&pwqkvl, g_wqkvl);
    cudaGetSymbolAddress((void**)&pwdh,   g_wdh);
    cudaGetSymbolAddress((void**)&pwdl,   g_wdl);
    cudaGetSymbolAddress((void**)&pw1h,   g_w1h);
    cudaGetSymbolAddress((void**)&pw1l,   g_w1l);
    cudaGetSymbolAddress((void**)&pw2h,   g_w2h);
    cudaGetSymbolAddress((void**)&pw2l,   g_w2l);

    cudaFuncSetAttribute(attn_kernel, cudaFuncAttributeMaxDynamicSharedMemorySize,
                         ATTN_SMEM_BYTES);
    cudaFuncSetAttribute(hgemm<0>, cudaFuncAttributeMaxDynamicSharedMemorySize, HM_SMEM);
    cudaFuncSetAttribute(hgemm<1>, cudaFuncAttributeMaxDynamicSharedMemorySize, HM_SMEM);
    cudaFuncSetAttribute(hgemm<2>, cudaFuncAttributeMaxDynamicSharedMemorySize, HM_SMEM);

    // weight splits (fp32 -> fp16 hi/lo)
    split_kernel<<<(3*Hdim*Hdim/2 + 255)/256, 256>>>(wqkv,   pwqkvh, pwqkvl, 3*Hdim*Hdim/2);
    split_kernel<<<(Hdim*Hdim/2   + 255)/256, 256>>>(wdense, pwdh,   pwdl,   Hdim*Hdim/2);
    split_kernel<<<(FFdim*Hdim/2  + 255)/256, 256>>>(w1,     pw1h,   pw1l,   FFdim*Hdim/2);
    split_kernel<<<(Hdim*FFdim/2  + 255)/256, 256>>>(w2,     pw2h,   pw2l,   Hdim*FFdim/2);
    // LN1 -> xh/xl
    ln_kernel<<<Mrows, 256>>>(hs, ln1w, ln1b, pxh, pxl);
    // RoPE trig table
    rope_table_kernel<<<(Sdim * 64) / 256, 256>>>();
    // QKV = x @ wqkv^T + bqkv (fp32 out for rope)
    hgemm<0><<<dim3(3 * Hdim / GBN, Mrows / GBM), 512, HM_SMEM>>>(
        pxh, pxl, pwqkvh, pwqkvl, bqkv, nullptr, pqkv, nullptr, nullptr,
        Mrows, 3 * Hdim, Hdim);
    // split + rope -> g_q, g_k, g_v in [B,NH,S,D]
    rope_kernel<<<dim3(Mrows, NHdim), 128>>>();
    // flash attention -> ctxh/ctxl in [B,S,H]
    attn_kernel<<<dim3(Sdim / ATT_BR, Bdim * NHdim), 256, ATTN_SMEM_BYTES>>>();
    // dense + residual(hidden_states) -> g_hidden (fp32)
    hgemm<2><<<dim3(Hdim / GBN, Mrows / GBM), 512, HM_SMEM>>>(
        pctxh, pctxl, pwdh, pwdl, bdense, hs, phid, nullptr, nullptr,
        Mrows, Hdim, Hdim);
    // LN2 -> xh/xl
    ln_kernel<<<Mrows, 256>>>(phid, ln2w, ln2b, pxh, pxl);
    // FF1 + GELU -> interh/interl (fp16 hi/lo)
    hgemm<1><<<dim3(FFdim / GBN, Mrows / GBM), 512, HM_SMEM>>>(
        pxh, pxl, pw1h, pw1l, b1, nullptr, nullptr, pinterh, pinterl,
        Mrows, FFdim, Hdim);
    // FF2 + residual(g_hidden) -> out
    hgemm<2><<<dim3(Hdim / GBN, Mrows / GBM), 512, HM_SMEM>>>(
        pinterh, pinterl, pw2h, pw2l, b2, phid, out, nullptr, nullptr,
        Mrows, Hdim, FFdim);
    // if output also carries the attention mask, convert it after hidden
    long long hid_elems = (long long)Mrows * Hdim;           // 8388608
    long long mask_elems = (long long)Sdim * Sdim;           // 4194304
    if ((long long)out_size >= hid_elems + mask_elems) {
        mask_kernel<<<(int)(mask_elems / 256), 256>>>(mask, out + hid_elems, (int)mask_elems);
    }
}

// round 7
// speedup vs baseline: 1.0356x; 1.0043x over previous
#include <cuda_runtime.h>
#include <cuda_fp16.h>
#include <cstdint>
#include <stdint.h>
#include <math.h>

// Problem constants
#define Bdim 2
#define Sdim 2048
#define Hdim 2048
#define NHdim 16
#define Ddim 128
#define FFdim 8192
#define Mrows (Bdim*Sdim)   // 4096

// -------- scratch (device globals; no allocation) --------
__device__ float g_qkv[(size_t)Mrows*3*Hdim];    // QKV gemm out (fp32, for rope)
__device__ float g_q[(size_t)Mrows*Hdim];        // [B,NH,S,D]
__device__ float g_k[(size_t)Mrows*Hdim];
__device__ float g_v[(size_t)Mrows*Hdim];
__device__ float g_hidden[(size_t)Mrows*Hdim];   // residual+attn_out
__device__ float g_cos[Sdim*64];
__device__ float g_sin[Sdim*64];
// fp16 hi/lo operand arrays
__device__ __half g_xh[(size_t)Mrows*Hdim],      g_xl[(size_t)Mrows*Hdim];
__device__ __half g_ctxh[(size_t)Mrows*Hdim],    g_ctxl[(size_t)Mrows*Hdim];
__device__ __half g_interh[(size_t)Mrows*FFdim], g_interl[(size_t)Mrows*FFdim];
__device__ __half g_wqkvh[(size_t)3*Hdim*Hdim],  g_wqkvl[(size_t)3*Hdim*Hdim];
__device__ __half g_wdh[(size_t)Hdim*Hdim],      g_wdl[(size_t)Hdim*Hdim];
__device__ __half g_w1h[(size_t)FFdim*Hdim],     g_w1l[(size_t)FFdim*Hdim];
__device__ __half g_w2h[(size_t)Hdim*FFdim],     g_w2l[(size_t)Hdim*FFdim];

// ============================ helpers ============================
__device__ __forceinline__ uint32_t smem_u32(const void* p) {
    uint32_t a;
    asm("{ .reg .u64 t; cvta.to.shared.u64 t, %1; cvt.u32.u64 %0, t; }" : "=r"(a) : "l"(p));
    return a;
}
__device__ __forceinline__ void ldsm4(uint32_t* r, uint32_t addr) {
    asm volatile("ldmatrix.sync.aligned.m8n8.x4.shared.b16 {%0,%1,%2,%3}, [%4];"
        : "=r"(r[0]), "=r"(r[1]), "=r"(r[2]), "=r"(r[3]) : "r"(addr));
}
// NOTE: non-volatile — pure register op; lets ptxas reorder/interleave MMAs
__device__ __forceinline__ void mma16816(float* c, const uint32_t* a, uint32_t b0, uint32_t b1) {
    asm("mma.sync.aligned.m16n8k16.row.col.f32.f16.f16.f32 "
        "{%0,%1,%2,%3}, {%4,%5,%6,%7}, {%8,%9}, {%0,%1,%2,%3};"
        : "+f"(c[0]), "+f"(c[1]), "+f"(c[2]), "+f"(c[3])
        : "r"(a[0]), "r"(a[1]), "r"(a[2]), "r"(a[3]), "r"(b0), "r"(b1));
}
__device__ __forceinline__ void cp16(uint32_t dst, const void* src) {
    asm volatile("cp.async.cg.shared.global [%0], [%1], 16;"
        :: "r"(dst), "l"(__cvta_generic_to_global(src)) : "memory");
}
#define CP_COMMIT() asm volatile("cp.async.commit_group;" ::: "memory")
#define CP_WAIT(n)  asm volatile("cp.async.wait_group %0;" :: "n"(n) : "memory")

// swizzled smem offset: rows of 64B (32 halfs), 16B chunk XOR (row>>1)&3
__device__ __forceinline__ uint32_t swoff(int row, int chunk) {
    return (uint32_t)(row * 64 + ((chunk ^ ((row >> 1) & 3)) << 4));
}
// split fp32 pair -> hi/lo half2
__device__ __forceinline__ void split2(float a, float b, __half2& h, __half2& l) {
    h = __floats2half2_rn(a, b);
    float2 hf = __half22float2(h);
    l = __floats2half2_rn(a - hf.x, b - hf.y);
}

// ============================ weight split kernel ============================
__global__ void split_kernel(const float* __restrict__ in, __half* __restrict__ hi,
                             __half* __restrict__ lo, int n2) {
    int i = blockIdx.x * blockDim.x + threadIdx.x;
    if (i >= n2) return;
    float2 v = *(const float2*)(in + (size_t)i * 2);
    __half2 h, l;
    split2(v.x, v.y, h, l);
    *(__half2*)(hi + (size_t)i * 2) = h;
    *(__half2*)(lo + (size_t)i * 2) = l;
}

// ============================ HMMA GEMM v4 (pass-major MMA ordering) ============================
// A: [M,K] half (Ah+Al), W: [N,K] half (Wh+Wl). 3-pass: AhWh + AlWh + AhWl.
// EPI: 0 = bias -> C fp32 ; 1 = bias+GELU -> Ch/Cl halves ; 2 = bias+residual -> C fp32
#define GBM 256
#define GBN 128
#define NSTAGE 3
#define STAGE_BYTES 49152     // Ah 16K | Al 16K | Wh 8K | Wl 8K
#define HM_SMEM (NSTAGE*STAGE_BYTES)

template<int EPI>
__global__ void __launch_bounds__(512, 1) hgemm(
    const __half* __restrict__ Ah_, const __half* __restrict__ Al_,
    const __half* __restrict__ Wh_, const __half* __restrict__ Wl_,
    const float* __restrict__ bias, const float* __restrict__ res,
    float* __restrict__ C, __half* __restrict__ Ch, __half* __restrict__ Cl,
    int M, int N, int K)
{
    extern __shared__ char sm[];
    uint32_t smb = smem_u32(sm);
    int tid = threadIdx.x;
    int lane = tid & 31, wid = tid >> 5;
    int wm = (wid & 3) * 64;       // 4 warp-rows over 256
    int wn = (wid >> 2) * 32;      // 4 warp-cols over 128
    int bm = blockIdx.y * GBM, bn = blockIdx.x * GBN;

    // loader coords: A -> 1024 chunk-slots (256 rows x 4 chunks), 2 per thread (same row)
    int aidx = tid * 2;
    int arow = aidx >> 2, ach = aidx & 3;
    // W -> 512 chunk-slots (128 rows x 4 chunks), 1 per thread
    int wrow = tid >> 2, wch = tid & 3;
    const __half* pAh = Ah_ + (size_t)(bm + arow) * K + ach * 8;
    const __half* pAl = Al_ + (size_t)(bm + arow) * K + ach * 8;
    const __half* pWh = Wh_ + (size_t)(bn + wrow) * K + wch * 8;
    const __half* pWl = Wl_ + (size_t)(bn + wrow) * K + wch * 8;
    uint32_t dA0 = swoff(arow, ach), dA1 = swoff(arow, ach + 1);
    uint32_t dW  = swoff(wrow, wch);

    float acc[4][4][4];
#pragma unroll
    for (int i = 0; i < 4; i++)
#pragma unroll
        for (int j = 0; j < 4; j++)
#pragma unroll
            for (int q = 0; q < 4; q++) acc[i][j][q] = 0.f;

    int mat = lane >> 3, mr = lane & 7;
    int fr_row = (mat & 1) * 8 + mr;
    int fr_ch  = mat >> 1;

    const int NC = K >> 5;

    auto load_stage = [&](int c) {
        uint32_t base = smb + (uint32_t)(c % NSTAGE) * STAGE_BYTES;
        size_t ko = (size_t)c * 32;
        cp16(base + 0     + dA0, pAh + ko);
        cp16(base + 0     + dA1, pAh + ko + 8);
        cp16(base + 16384 + dA0, pAl + ko);
        cp16(base + 16384 + dA1, pAl + ko + 8);
        cp16(base + 32768 + dW,  pWh + ko);
        cp16(base + 40960 + dW,  pWl + ko);
    };

    // prologue: 2 stages in flight
#pragma unroll
    for (int c = 0; c < NSTAGE - 1; c++) { load_stage(c); CP_COMMIT(); }

    for (int c = 0; c < NC; c++) {
        CP_WAIT(NSTAGE - 2);
        __syncthreads();
        if (c + NSTAGE - 1 < NC) { load_stage(c + NSTAGE - 1); }
        CP_COMMIT();

        uint32_t base = smb + (uint32_t)(c % NSTAGE) * STAGE_BYTES;
#pragma unroll
        for (int kk = 0; kk < 2; kk++) {
            uint32_t ah[4][4], al[4][4], bh[2][4];
#pragma unroll
            for (int i = 0; i < 4; i++) {
                uint32_t off = swoff(wm + i * 16 + fr_row, kk * 2 + fr_ch);
                ldsm4(ah[i], base + 0     + off);
                ldsm4(al[i], base + 16384 + off);
            }
#pragma unroll
            for (int g = 0; g < 2; g++) {
                uint32_t off = swoff(wn + g * 16 + fr_row, kk * 2 + fr_ch);
                ldsm4(bh[g], base + 32768 + off);
            }
            // pass 1: ah*bh — 16 MMAs, all-distinct accumulators
#pragma unroll
            for (int i = 0; i < 4; i++) {
#pragma unroll
                for (int jj = 0; jj < 4; jj++) {
                    int g = jj >> 1, h = jj & 1;
                    mma16816(acc[i][jj], ah[i], bh[g][h], bh[g][h+2]);
                }
            }
            // pass 2: al*bh — 16 MMAs (reuse distance 16 from pass 1)
#pragma unroll
            for (int i = 0; i < 4; i++) {
#pragma unroll
                for (int jj = 0; jj < 4; jj++) {
                    int g = jj >> 1, h = jj & 1;
                    mma16816(acc[i][jj], al[i], bh[g][h], bh[g][h+2]);
                }
            }
            // pass 3: ah*bl (bl loaded after al is dead)
            uint32_t bl[2][4];
#pragma unroll
            for (int g = 0; g < 2; g++) {
                uint32_t off = swoff(wn + g * 16 + fr_row, kk * 2 + fr_ch);
                ldsm4(bl[g], base + 40960 + off);
            }
#pragma unroll
            for (int i = 0; i < 4; i++) {
#pragma unroll
                for (int jj = 0; jj < 4; jj++) {
                    int g = jj >> 1, h = jj & 1;
                    mma16816(acc[i][jj], ah[i], bl[g][h], bl[g][h+2]);
                }
            }
        }
    }

    // epilogue
    int tr = lane >> 2;
    int tc = (lane & 3) * 2;
#pragma unroll
    for (int i = 0; i < 4; i++) {
#pragma unroll
        for (int jj = 0; jj < 4; jj++) {
            int n0 = bn + wn + jj * 8 + tc;
            float b0 = bias[n0], b1 = bias[n0 + 1];
#pragma unroll
            for (int half = 0; half < 2; half++) {
                int m = bm + wm + i * 16 + tr + half * 8;
                size_t idx = (size_t)m * N + n0;
                float v0 = acc[i][jj][half * 2 + 0] + b0;
                float v1 = acc[i][jj][half * 2 + 1] + b1;
                if (EPI == 1) {
                    v0 = 0.5f * v0 * (1.0f + erff(v0 * 0.70710678118654752f));
                    v1 = 0.5f * v1 * (1.0f + erff(v1 * 0.70710678118654752f));
                    __half2 h, l;
                    split2(v0, v1, h, l);
                    *(__half2*)(Ch + idx) = h;
                    *(__half2*)(Cl + idx) = l;
                } else {
                    if (EPI == 2) { v0 += res[idx]; v1 += res[idx + 1]; }
                    *(float2*)(C + idx) = make_float2(v0, v1);
                }
            }
        }
    }
}

// ============================ LayerNorm -> fp16 hi/lo ============================
__global__ void ln_kernel(const float* __restrict__ in, const float* __restrict__ w,
                          const float* __restrict__ b,
                          __half* __restrict__ oh, __half* __restrict__ ol) {
    __shared__ float2 red[256];
    int row = blockIdx.x;
    const float* x = in + (size_t)row * Hdim;
    float s = 0.f, ss = 0.f;
    for (int i = threadIdx.x * 2; i < Hdim; i += 512) {
        float2 v = *(const float2*)(x + i);
        s += v.x + v.y;
        ss = fmaf(v.x, v.x, fmaf(v.y, v.y, ss));
    }
    red[threadIdx.x] = make_float2(s, ss);
    __syncthreads();
    for (int o = 128; o > 0; o >>= 1) {
        if (threadIdx.x < o) {
            float2 a = red[threadIdx.x], c = red[threadIdx.x + o];
            red[threadIdx.x] = make_float2(a.x + c.x, a.y + c.y);
        }
        __syncthreads();
    }
    float mean = red[0].x * (1.0f / Hdim);
    float var  = red[0].y * (1.0f / Hdim) - mean * mean;
    float rstd = rsqrtf(var + 1e-5f);
    for (int i = threadIdx.x * 2; i < Hdim; i += 512) {
        float2 v = *(const float2*)(x + i);
        float2 wv = *(const float2*)(w + i);
        float2 bv = *(const float2*)(b + i);
        float o0 = (v.x - mean) * rstd * wv.x + bv.x;
        float o1 = (v.y - mean) * rstd * wv.y + bv.y;
        __half2 h, l;
        split2(o0, o1, h, l);
        *(__half2*)(oh + (size_t)row * Hdim + i) = h;
        *(__half2*)(ol + (size_t)row * Hdim + i) = l;
    }
}

// ============================ RoPE table (double precision trig) ============================
__global__ void rope_table_kernel() {
    int idx = blockIdx.x * blockDim.x + threadIdx.x;
    if (idx >= Sdim * 64) return;
    int s = idx >> 6, i = idx & 63;
    double invf = exp(-(double)i * (9.210340371976184 / 64.0)); // ln(10000)/64
    double th = (double)s * invf;
    g_cos[idx] = (float)cos(th);
    g_sin[idx] = (float)sin(th);
}

// ============================ QKV split + RoPE ============================
__global__ void rope_kernel() {
    int row = blockIdx.x;      // b*S + s
    int h = blockIdx.y;
    int d = threadIdx.x;       // 0..127
    int s = row & (Sdim - 1);
    int b = row >> 11;
    const float* src = g_qkv + (size_t)row * (3 * Hdim) + h * (3 * Ddim);
    float q = src[d];
    float k = src[Ddim + d];
    float v = src[2 * Ddim + d];
    int di = d & 63;
    float cs = g_cos[s * 64 + di];
    float sn = g_sin[s * 64 + di];
    float qp, kp;
    if (d < 64) { qp = -src[d + 64];        kp = -src[Ddim + d + 64]; }
    else        { qp =  src[d - 64];        kp =  src[Ddim + d - 64]; }
    size_t oidx = ((size_t)(b * NHdim + h) * Sdim + s) * Ddim + d;
    g_q[oidx] = q * cs + qp * sn;
    g_k[oidx] = k * cs + kp * sn;
    g_v[oidx] = v;
}

// ============================ Flash attention (fp32, causal) ============================
#define ATT_BR 64
#define ATT_BC 32
#define ATT_PD 132
#define ATT_PS 36
#define ATTN_SMEM_BYTES ((ATT_BR*ATT_PD + 2*ATT_BC*ATT_PD + ATT_BR*ATT_PS + 3*ATT_BR) * 4)

__global__ void __launch_bounds__(256) attn_kernel() {
    extern __shared__ float smf[];
    float* Qs  = smf;
    float* Ks  = Qs + ATT_BR * ATT_PD;
    float* Vs  = Ks + ATT_BC * ATT_PD;
    float* Ss  = Vs + ATT_BC * ATT_PD;
    float* m_s = Ss + ATT_BR * ATT_PS;
    float* l_s = m_s + ATT_BR;
    float* sc_s = l_s + ATT_BR;

    int qt = gridDim.x - 1 - blockIdx.x;
    int bh = blockIdx.y;
    int tid = threadIdx.x;
    int ty = tid >> 4, tx = tid & 15;

    const float* Qg = g_q + ((size_t)bh * Sdim + (size_t)qt * ATT_BR) * Ddim;
    const float* Kg = g_k + (size_t)bh * Sdim * Ddim;
    const float* Vg = g_v + (size_t)bh * Sdim * Ddim;

    for (int i = tid * 4; i < ATT_BR * Ddim; i += 1024) {
        float4 v = *(const float4*)(Qg + i);
        int r = i >> 7, c = i & 127;
        float* q = Qs + r * ATT_PD + c;
        q[0] = v.x; q[1] = v.y; q[2] = v.z; q[3] = v.w;
    }
    if (tid < ATT_BR) { m_s[tid] = -INFINITY; l_s[tid] = 0.f; }

    float acc[4][8];
#pragma unroll
    for (int i = 0; i < 4; i++)
#pragma unroll
        for (int j = 0; j < 8; j++) acc[i][j] = 0.f;

    int nkt = 2 * qt + 2;
    for (int kt = 0; kt < nkt; kt++) {
        __syncthreads();
        const float* Kt = Kg + (size_t)kt * ATT_BC * Ddim;
        const float* Vt = Vg + (size_t)kt * ATT_BC * Ddim;
        for (int i = tid * 4; i < ATT_BC * Ddim; i += 1024) {
            float4 kv = *(const float4*)(Kt + i);
            float4 vv = *(const float4*)(Vt + i);
            int r = i >> 7, c = i & 127;
            float* kp = Ks + r * ATT_PD + c;
            kp[0] = kv.x; kp[1] = kv.y; kp[2] = kv.z; kp[3] = kv.w;
            float* vp = Vs + r * ATT_PD + c;
            vp[0] = vv.x; vp[1] = vv.y; vp[2] = vv.z; vp[3] = vv.w;
        }
        __syncthreads();

        float sa[4][2];
#pragma unroll
        for (int i = 0; i < 4; i++) { sa[i][0] = 0.f; sa[i][1] = 0.f; }
        const float* q0 = Qs + (ty * 4) * ATT_PD;
        const float* k0 = Ks + (tx * 2) * ATT_PD;
        for (int k = 0; k < Ddim; k += 4) {
            float4 b0 = *(const float4*)(k0 + k);
            float4 b1 = *(const float4*)(k0 + ATT_PD + k);
#pragma unroll
            for (int i = 0; i < 4; i++) {
                float4 a = *(const float4*)(q0 + i * ATT_PD + k);
                sa[i][0] += a.x * b0.x + a.y * b0.y + a.z * b0.z + a.w * b0.w;
                sa[i][1] += a.x * b1.x + a.y * b1.y + a.z * b1.z + a.w * b1.w;
            }
        }
        int qbase = qt * ATT_BR + ty * 4;
        int kbase = kt * ATT_BC + tx * 2;
#pragma unroll
        for (int i = 0; i < 4; i++) {
#pragma unroll
            for (int j = 0; j < 2; j++) {
                float v = sa[i][j] * 0.08838834764831845f;
                if (kbase + j > qbase + i) v = -1e30f;
                Ss[(ty * 4 + i) * ATT_PS + tx * 2 + j] = v;
            }
        }
        __syncthreads();

        if (tid < ATT_BR) {
            float mold = m_s[tid];
            float mnew = mold;
            float* srow = Ss + tid * ATT_PS;
#pragma unroll
            for (int c = 0; c < ATT_BC; c++) mnew = fmaxf(mnew, srow[c]);
            float lsum = 0.f;
#pragma unroll
            for (int c = 0; c < ATT_BC; c++) {
                float p = expf(srow[c] - mnew);
                srow[c] = p;
                lsum += p;
            }
            float scl = expf(mold - mnew);
            sc_s[tid] = scl;
            l_s[tid] = l_s[tid] * scl + lsum;
            m_s[tid] = mnew;
        }
        __syncthreads();

#pragma unroll
        for (int i = 0; i < 4; i++) {
            float scl = sc_s[ty * 4 + i];
#pragma unroll
            for (int j = 0; j < 8; j++) acc[i][j] *= scl;
        }
        const float* s0 = Ss + (ty * 4) * ATT_PS;
        const float* v0 = Vs + tx * 8;
        for (int c = 0; c < ATT_BC; c += 4) {
            float pr[4][4];
            *(float4*)pr[0] = *(const float4*)(s0 + 0 * ATT_PS + c);
            *(float4*)pr[1] = *(const float4*)(s0 + 1 * ATT_PS + c);
            *(float4*)pr[2] = *(const float4*)(s0 + 2 * ATT_PS + c);
            *(float4*)pr[3] = *(const float4*)(s0 + 3 * ATT_PS + c);
#pragma unroll
            for (int cc = 0; cc < 4; cc++) {
                float4 va = *(const float4*)(v0 + (c + cc) * ATT_PD);
                float4 vb = *(const float4*)(v0 + (c + cc) * ATT_PD + 4);
#pragma unroll
                for (int i = 0; i < 4; i++) {
                    float p = pr[i][cc];
                    acc[i][0] = fmaf(p, va.x, acc[i][0]);
                    acc[i][1] = fmaf(p, va.y, acc[i][1]);
                    acc[i][2] = fmaf(p, va.z, acc[i][2]);
                    acc[i][3] = fmaf(p, va.w, acc[i][3]);
                    acc[i][4] = fmaf(p, vb.x, acc[i][4]);
                    acc[i][5] = fmaf(p, vb.y, acc[i][5]);
                    acc[i][6] = fmaf(p, vb.z, acc[i][6]);
                    acc[i][7] = fmaf(p, vb.w, acc[i][7]);
                }
            }
        }
    }

    // write ctx as fp16 hi/lo in [B,S,H]
    int b = bh >> 4, h = bh & 15;
#pragma unroll
    for (int i = 0; i < 4; i++) {
        int r = ty * 4 + i;
        int sg = qt * ATT_BR + r;
        float inv = 1.0f / l_s[r];
        size_t off = ((size_t)(b * Sdim + sg) * Hdim) + h * Ddim + tx * 8;
#pragma unroll
        for (int j = 0; j < 8; j += 2) {
            float a0 = acc[i][j] * inv, a1 = acc[i][j + 1] * inv;
            __half2 hh, ll;
            split2(a0, a1, hh, ll);
            *(__half2*)(g_ctxh + off + j) = hh;
            *(__half2*)(g_ctxl + off + j) = ll;
        }
    }
}

// ============================ mask passthrough ============================
__global__ void mask_kernel(const unsigned char* __restrict__ m, float* __restrict__ o, int n) {
    int i = blockIdx.x * blockDim.x + threadIdx.x;
    if (i < n) o[i] = m[i] ? 1.0f : 0.0f;
}

// ============================ launch ============================
extern "C" void kernel_launch(void* const* d_in, const int* in_sizes, int n_in,
                              void* d_out, int out_size) {
    const float* hs            = (const float*)d_in[0];
    const unsigned char* mask  = (const unsigned char*)d_in[1];
    const float* ln1w          = (const float*)d_in[2];
    const float* ln1b          = (const float*)d_in[3];
    const float* wqkv          = (const float*)d_in[4];
    const float* bqkv          = (const float*)d_in[5];
    const float* wdense        = (const float*)d_in[6];
    const float* bdense        = (const float*)d_in[7];
    const float* ln2w          = (const float*)d_in[8];
    const float* ln2b          = (const float*)d_in[9];
    const float* w1            = (const float*)d_in[10];
    const float* b1            = (const float*)d_in[11];
    const float* w2            = (const float*)d_in[12];
    const float* b2            = (const float*)d_in[13];
    float* out = (float*)d_out;

    float *pqkv, *phid;
    __half *pxh, *pxl, *pctxh, *pctxl, *pinterh, *pinterl;
    __half *pwqkvh, *pwqkvl, *pwdh, *pwdl, *pw1h, *pw1l, *pw2h, *pw2l;
    cudaGetSymbolAddress((void**)&pqkv,   g_qkv);
    cudaGetSymbolAddress((void**)&phid,   g_hidden);
    cudaGetSymbolAddress((void**)&pxh,    g_xh);
    cudaGetSymbolAddress((void**)&pxl,    g_xl);
    cudaGetSymbolAddress((void**)&pctxh,  g_ctxh);
    cudaGetSymbolAddress((void**)&pctxl,  g_ctxl);
    cudaGetSymbolAddress((void**)&pinterh, g_interh);
    cudaGetSymbolAddress((void**)&pinterl, g_interl);
    cudaGetSymbolAddress((void**)&pwqkvh, g_wqkvh);
    cudaGetSymbolAddress((void**)&pwqkvl, g_wqkvl);
    cudaGetSymbolAddress((void**)&pwdh,   g_wdh);
    cudaGetSymbolAddress((void**)&pwdl,   g_wdl);
    cudaGetSymbolAddress((void**)&pw1h,   g_w1h);
    cudaGetSymbolAddress((void**)&pw1l,   g_w1l);
    cudaGetSymbolAddress((void**)&pw2h,   g_w2h);
    cudaGetSymbolAddress((void**)&pw2l,   g_w2l);

    cudaFuncSetAttribute(attn_kernel, cudaFuncAttributeMaxDynamicSharedMemorySize,
                         ATTN_SMEM_BYTES);
    cudaFuncSetAttribute(hgemm<0>, cudaFuncAttributeMaxDynamicSharedMemorySize, HM_SMEM);
    cudaFuncSetAttribute(hgemm<1>, cudaFuncAttributeMaxDynamicSharedMemorySize, HM_SMEM);
    cudaFuncSetAttribute(hgemm<2>, cudaFuncAttributeMaxDynamicSharedMemorySize, HM_SMEM);

    // weight splits (fp32 -> fp16 hi/lo)
    split_kernel<<<(3*Hdim*Hdim/2 + 255)/256, 256>>>(wqkv,   pwqkvh, pwqkvl, 3*Hdim*Hdim/2);
    split_kernel<<<(Hdim*Hdim/2   + 255)/256, 256>>>(wdense, pwdh,   pwdl,   Hdim*Hdim/2);
    split_kernel<<<(FFdim*Hdim/2  + 255)/256, 256>>>(w1,     pw1h,   pw1l,   FFdim*Hdim/2);
    split_kernel<<<(Hdim*FFdim/2  + 255)/256, 256>>>(w2,     pw2h,   pw2l,   Hdim*FFdim/2);
    // LN1 -> xh/xl
    ln_kernel<<<Mrows, 256>>>(hs, ln1w, ln1b, pxh, pxl);
    // RoPE trig table
    rope_table_kernel<<<(Sdim * 64) / 256, 256>>>();
    // QKV = x @ wqkv^T + bqkv (fp32 out for rope)
    hgemm<0><<<dim3(3 * Hdim / GBN, Mrows / GBM), 512, HM_SMEM>>>(
        pxh, pxl, pwqkvh, pwqkvl, bqkv, nullptr, pqkv, nullptr, nullptr,
        Mrows, 3 * Hdim, Hdim);
    // split + rope -> g_q, g_k, g_v in [B,NH,S,D]
    rope_kernel<<<dim3(Mrows, NHdim), 128>>>();
    // flash attention -> ctxh/ctxl in [B,S,H]
    attn_kernel<<<dim3(Sdim / ATT_BR, Bdim * NHdim), 256, ATTN_SMEM_BYTES>>>();
    // dense + residual(hidden_states) -> g_hidden (fp32)
    hgemm<2><<<dim3(Hdim / GBN, Mrows / GBM), 512, HM_SMEM>>>(
        pctxh, pctxl, pwdh, pwdl, bdense, hs, phid, nullptr, nullptr,
        Mrows, Hdim, Hdim);
    // LN2 -> xh/xl
    ln_kernel<<<Mrows, 256>>>(phid, ln2w, ln2b, pxh, pxl);
    // FF1 + GELU -> interh/interl (fp16 hi/lo)
    hgemm<1><<<dim3(FFdim / GBN, Mrows / GBM), 512, HM_SMEM>>>(
        pxh, pxl, pw1h, pw1l, b1, nullptr, nullptr, pinterh, pinterl,
        Mrows, FFdim, Hdim);
    // FF2 + residual(g_hidden) -> out
    hgemm<2><<<dim3(Hdim / GBN, Mrows / GBM), 512, HM_SMEM>>>(
        pinterh, pinterl, pw2h, pw2l, b2, phid, out, nullptr, nullptr,
        Mrows, Hdim, FFdim);
    // if output also carries the attention mask, convert it after hidden
    long long hid_elems = (long long)Mrows * Hdim;           // 8388608
    long long mask_elems = (long long)Sdim * Sdim;           // 4194304
    if ((long long)out_size >= hid_elems + mask_elems) {
        mask_kernel<<<(int)(mask_elems / 256), 256>>>(mask, out + hid_elems, (int)mask_elems);
    }
}

// round 8
// speedup vs baseline: 1.1970x; 1.1559x over previous
#include <cuda_runtime.h>
#include <cuda_fp16.h>
#include <cstdint>
#include <stdint.h>
#include <math.h>

// Problem constants
#define Bdim 2
#define Sdim 2048
#define Hdim 2048
#define NHdim 16
#define Ddim 128
#define FFdim 8192
#define Mrows (Bdim*Sdim)   // 4096

// -------- scratch (device globals; no allocation) --------
__device__ float g_qkv[(size_t)Mrows*3*Hdim];    // QKV gemm out (fp32, for rope)
__device__ float g_q[(size_t)Mrows*Hdim];        // [B,NH,S,D]
__device__ float g_k[(size_t)Mrows*Hdim];
__device__ float g_v[(size_t)Mrows*Hdim];
__device__ float g_hidden[(size_t)Mrows*Hdim];   // residual+attn_out
__device__ float g_cos[Sdim*64];
__device__ float g_sin[Sdim*64];
// fp16 hi/lo operand arrays
__device__ __half g_xh[(size_t)Mrows*Hdim],      g_xl[(size_t)Mrows*Hdim];
__device__ __half g_ctxh[(size_t)Mrows*Hdim],    g_ctxl[(size_t)Mrows*Hdim];
__device__ __half g_interh[(size_t)Mrows*FFdim], g_interl[(size_t)Mrows*FFdim];
__device__ __half g_wqkvh[(size_t)3*Hdim*Hdim],  g_wqkvl[(size_t)3*Hdim*Hdim];
__device__ __half g_wdh[(size_t)Hdim*Hdim];
__device__ __half g_w1h[(size_t)FFdim*Hdim];
__device__ __half g_w2h[(size_t)Hdim*FFdim];

// ============================ helpers ============================
__device__ __forceinline__ uint32_t smem_u32(const void* p) {
    uint32_t a;
    asm("{ .reg .u64 t; cvta.to.shared.u64 t, %1; cvt.u32.u64 %0, t; }" : "=r"(a) : "l"(p));
    return a;
}
__device__ __forceinline__ void ldsm4(uint32_t* r, uint32_t addr) {
    asm volatile("ldmatrix.sync.aligned.m8n8.x4.shared.b16 {%0,%1,%2,%3}, [%4];"
        : "=r"(r[0]), "=r"(r[1]), "=r"(r[2]), "=r"(r[3]) : "r"(addr));
}
__device__ __forceinline__ void mma16816(float* c, const uint32_t* a, uint32_t b0, uint32_t b1) {
    asm("mma.sync.aligned.m16n8k16.row.col.f32.f16.f16.f32 "
        "{%0,%1,%2,%3}, {%4,%5,%6,%7}, {%8,%9}, {%0,%1,%2,%3};"
        : "+f"(c[0]), "+f"(c[1]), "+f"(c[2]), "+f"(c[3])
        : "r"(a[0]), "r"(a[1]), "r"(a[2]), "r"(a[3]), "r"(b0), "r"(b1));
}
__device__ __forceinline__ void cp16(uint32_t dst, const void* src) {
    asm volatile("cp.async.cg.shared.global [%0], [%1], 16;"
        :: "r"(dst), "l"(__cvta_generic_to_global(src)) : "memory");
}
#define CP_COMMIT() asm volatile("cp.async.commit_group;" ::: "memory")
#define CP_WAIT(n)  asm volatile("cp.async.wait_group %0;" :: "n"(n) : "memory")

// swizzled smem offset: rows of 64B (32 halfs), 16B chunk XOR (row>>1)&3
__device__ __forceinline__ uint32_t swoff(int row, int chunk) {
    return (uint32_t)(row * 64 + ((chunk ^ ((row >> 1) & 3)) << 4));
}
// split fp32 pair -> hi/lo half2
__device__ __forceinline__ void split2(float a, float b, __half2& h, __half2& l) {
    h = __floats2half2_rn(a, b);
    float2 hf = __half22float2(h);
    l = __floats2half2_rn(a - hf.x, b - hf.y);
}

// ============================ weight split kernels ============================
__global__ void split_kernel(const float* __restrict__ in, __half* __restrict__ hi,
                             __half* __restrict__ lo, int n2) {
    int i = blockIdx.x * blockDim.x + threadIdx.x;
    if (i >= n2) return;
    float2 v = *(const float2*)(in + (size_t)i * 2);
    __half2 h, l;
    split2(v.x, v.y, h, l);
    *(__half2*)(hi + (size_t)i * 2) = h;
    *(__half2*)(lo + (size_t)i * 2) = l;
}
__global__ void cvt_kernel(const float* __restrict__ in, __half* __restrict__ hi, int n2) {
    int i = blockIdx.x * blockDim.x + threadIdx.x;
    if (i >= n2) return;
    float2 v = *(const float2*)(in + (size_t)i * 2);
    *(__half2*)(hi + (size_t)i * 2) = __floats2half2_rn(v.x, v.y);
}

// ============================ HMMA GEMM v5 (selectable pass count) ============================
// A: [M,K] half (Ah+Al exact to 22 bits), W: [N,K] half.
// NPASS=3: AhWh + AlWh + AhWl (W 22-bit).  NPASS=2: AhWh + AlWh (W 11-bit).
// EPI: 0 = bias -> C fp32 ; 1 = bias+GELU -> Ch/Cl halves ; 2 = bias+residual -> C fp32
#define GBM 256
#define GBN 128
#define NSTAGE 3
#define STAGE3 49152     // Ah 16K | Al 16K | Wh 8K | Wl 8K
#define STAGE2 40960     // Ah 16K | Al 16K | Wh 8K
#define HM_SMEM3 (NSTAGE*STAGE3)
#define HM_SMEM2 (NSTAGE*STAGE2)

template<int EPI, int NPASS>
__global__ void __launch_bounds__(512, 1) hgemm(
    const __half* __restrict__ Ah_, const __half* __restrict__ Al_,
    const __half* __restrict__ Wh_, const __half* __restrict__ Wl_,
    const float* __restrict__ bias, const float* __restrict__ res,
    float* __restrict__ C, __half* __restrict__ Ch, __half* __restrict__ Cl,
    int M, int N, int K)
{
    constexpr int SB = (NPASS == 3) ? STAGE3 : STAGE2;
    extern __shared__ char sm[];
    uint32_t smb = smem_u32(sm);
    int tid = threadIdx.x;
    int lane = tid & 31, wid = tid >> 5;
    int wm = (wid & 3) * 64;       // 4 warp-rows over 256
    int wn = (wid >> 2) * 32;      // 4 warp-cols over 128
    int bm = blockIdx.y * GBM, bn = blockIdx.x * GBN;

    // loader coords
    int aidx = tid * 2;
    int arow = aidx >> 2, ach = aidx & 3;
    int wrow = tid >> 2, wch = tid & 3;
    const __half* pAh = Ah_ + (size_t)(bm + arow) * K + ach * 8;
    const __half* pAl = Al_ + (size_t)(bm + arow) * K + ach * 8;
    const __half* pWh = Wh_ + (size_t)(bn + wrow) * K + wch * 8;
    const __half* pWl = (NPASS == 3) ? (Wl_ + (size_t)(bn + wrow) * K + wch * 8) : nullptr;
    uint32_t dA0 = swoff(arow, ach), dA1 = swoff(arow, ach + 1);
    uint32_t dW  = swoff(wrow, wch);

    float acc[4][4][4];
#pragma unroll
    for (int i = 0; i < 4; i++)
#pragma unroll
        for (int j = 0; j < 4; j++)
#pragma unroll
            for (int q = 0; q < 4; q++) acc[i][j][q] = 0.f;

    int mat = lane >> 3, mr = lane & 7;
    int fr_row = (mat & 1) * 8 + mr;
    int fr_ch  = mat >> 1;

    const int NC = K >> 5;

    auto load_stage = [&](int c) {
        uint32_t base = smb + (uint32_t)(c % NSTAGE) * SB;
        size_t ko = (size_t)c * 32;
        cp16(base + 0     + dA0, pAh + ko);
        cp16(base + 0     + dA1, pAh + ko + 8);
        cp16(base + 16384 + dA0, pAl + ko);
        cp16(base + 16384 + dA1, pAl + ko + 8);
        cp16(base + 32768 + dW,  pWh + ko);
        if (NPASS == 3) cp16(base + 40960 + dW, pWl + ko);
    };

    // prologue: 2 stages in flight
#pragma unroll
    for (int c = 0; c < NSTAGE - 1; c++) { load_stage(c); CP_COMMIT(); }

    for (int c = 0; c < NC; c++) {
        CP_WAIT(NSTAGE - 2);
        __syncthreads();
        if (c + NSTAGE - 1 < NC) { load_stage(c + NSTAGE - 1); }
        CP_COMMIT();

        uint32_t base = smb + (uint32_t)(c % NSTAGE) * SB;
#pragma unroll
        for (int kk = 0; kk < 2; kk++) {
            uint32_t ah[4][4], al[4][4], bh[2][4];
#pragma unroll
            for (int i = 0; i < 4; i++) {
                uint32_t off = swoff(wm + i * 16 + fr_row, kk * 2 + fr_ch);
                ldsm4(ah[i], base + 0     + off);
                ldsm4(al[i], base + 16384 + off);
            }
#pragma unroll
            for (int g = 0; g < 2; g++) {
                uint32_t off = swoff(wn + g * 16 + fr_row, kk * 2 + fr_ch);
                ldsm4(bh[g], base + 32768 + off);
            }
            // pass 1: ah*bh
#pragma unroll
            for (int i = 0; i < 4; i++) {
#pragma unroll
                for (int jj = 0; jj < 4; jj++) {
                    int g = jj >> 1, h = jj & 1;
                    mma16816(acc[i][jj], ah[i], bh[g][h], bh[g][h+2]);
                }
            }
            // pass 2: al*bh
#pragma unroll
            for (int i = 0; i < 4; i++) {
#pragma unroll
                for (int jj = 0; jj < 4; jj++) {
                    int g = jj >> 1, h = jj & 1;
                    mma16816(acc[i][jj], al[i], bh[g][h], bh[g][h+2]);
                }
            }
            // pass 3 (NPASS==3 only): ah*bl
            if (NPASS == 3) {
                uint32_t bl[2][4];
#pragma unroll
                for (int g = 0; g < 2; g++) {
                    uint32_t off = swoff(wn + g * 16 + fr_row, kk * 2 + fr_ch);
                    ldsm4(bl[g], base + 40960 + off);
                }
#pragma unroll
                for (int i = 0; i < 4; i++) {
#pragma unroll
                    for (int jj = 0; jj < 4; jj++) {
                        int g = jj >> 1, h = jj & 1;
                        mma16816(acc[i][jj], ah[i], bl[g][h], bl[g][h+2]);
                    }
                }
            }
        }
    }

    // epilogue
    int tr = lane >> 2;
    int tc = (lane & 3) * 2;
#pragma unroll
    for (int i = 0; i < 4; i++) {
#pragma unroll
        for (int jj = 0; jj < 4; jj++) {
            int n0 = bn + wn + jj * 8 + tc;
            float b0 = bias[n0], b1 = bias[n0 + 1];
#pragma unroll
            for (int half = 0; half < 2; half++) {
                int m = bm + wm + i * 16 + tr + half * 8;
                size_t idx = (size_t)m * N + n0;
                float v0 = acc[i][jj][half * 2 + 0] + b0;
                float v1 = acc[i][jj][half * 2 + 1] + b1;
                if (EPI == 1) {
                    v0 = 0.5f * v0 * (1.0f + erff(v0 * 0.70710678118654752f));
                    v1 = 0.5f * v1 * (1.0f + erff(v1 * 0.70710678118654752f));
                    __half2 h, l;
                    split2(v0, v1, h, l);
                    *(__half2*)(Ch + idx) = h;
                    *(__half2*)(Cl + idx) = l;
                } else {
                    if (EPI == 2) { v0 += res[idx]; v1 += res[idx + 1]; }
                    *(float2*)(C + idx) = make_float2(v0, v1);
                }
            }
        }
    }
}

// ============================ LayerNorm -> fp16 hi/lo ============================
__global__ void ln_kernel(const float* __restrict__ in, const float* __restrict__ w,
                          const float* __restrict__ b,
                          __half* __restrict__ oh, __half* __restrict__ ol) {
    __shared__ float2 red[256];
    int row = blockIdx.x;
    const float* x = in + (size_t)row * Hdim;
    float s = 0.f, ss = 0.f;
    for (int i = threadIdx.x * 2; i < Hdim; i += 512) {
        float2 v = *(const float2*)(x + i);
        s += v.x + v.y;
        ss = fmaf(v.x, v.x, fmaf(v.y, v.y, ss));
    }
    red[threadIdx.x] = make_float2(s, ss);
    __syncthreads();
    for (int o = 128; o > 0; o >>= 1) {
        if (threadIdx.x < o) {
            float2 a = red[threadIdx.x], c = red[threadIdx.x + o];
            red[threadIdx.x] = make_float2(a.x + c.x, a.y + c.y);
        }
        __syncthreads();
    }
    float mean = red[0].x * (1.0f / Hdim);
    float var  = red[0].y * (1.0f / Hdim) - mean * mean;
    float rstd = rsqrtf(var + 1e-5f);
    for (int i = threadIdx.x * 2; i < Hdim; i += 512) {
        float2 v = *(const float2*)(x + i);
        float2 wv = *(const float2*)(w + i);
        float2 bv = *(const float2*)(b + i);
        float o0 = (v.x - mean) * rstd * wv.x + bv.x;
        float o1 = (v.y - mean) * rstd * wv.y + bv.y;
        __half2 h, l;
        split2(o0, o1, h, l);
        *(__half2*)(oh + (size_t)row * Hdim + i) = h;
        *(__half2*)(ol + (size_t)row * Hdim + i) = l;
    }
}

// ============================ RoPE table (double precision trig) ============================
__global__ void rope_table_kernel() {
    int idx = blockIdx.x * blockDim.x + threadIdx.x;
    if (idx >= Sdim * 64) return;
    int s = idx >> 6, i = idx & 63;
    double invf = exp(-(double)i * (9.210340371976184 / 64.0)); // ln(10000)/64
    double th = (double)s * invf;
    g_cos[idx] = (float)cos(th);
    g_sin[idx] = (float)sin(th);
}

// ============================ QKV split + RoPE ============================
__global__ void rope_kernel() {
    int row = blockIdx.x;      // b*S + s
    int h = blockIdx.y;
    int d = threadIdx.x;       // 0..127
    int s = row & (Sdim - 1);
    int b = row >> 11;
    const float* src = g_qkv + (size_t)row * (3 * Hdim) + h * (3 * Ddim);
    float q = src[d];
    float k = src[Ddim + d];
    float v = src[2 * Ddim + d];
    int di = d & 63;
    float cs = g_cos[s * 64 + di];
    float sn = g_sin[s * 64 + di];
    float qp, kp;
    if (d < 64) { qp = -src[d + 64];        kp = -src[Ddim + d + 64]; }
    else        { qp =  src[d - 64];        kp =  src[Ddim + d - 64]; }
    size_t oidx = ((size_t)(b * NHdim + h) * Sdim + s) * Ddim + d;
    g_q[oidx] = q * cs + qp * sn;
    g_k[oidx] = k * cs + kp * sn;
    g_v[oidx] = v;
}

// ============================ Flash attention (fp32, causal) ============================
#define ATT_BR 64
#define ATT_BC 32
#define ATT_PD 132
#define ATT_PS 36
#define ATTN_SMEM_BYTES ((ATT_BR*ATT_PD + 2*ATT_BC*ATT_PD + ATT_BR*ATT_PS + 3*ATT_BR) * 4)

__global__ void __launch_bounds__(256) attn_kernel() {
    extern __shared__ float smf[];
    float* Qs  = smf;
    float* Ks  = Qs + ATT_BR * ATT_PD;
    float* Vs  = Ks + ATT_BC * ATT_PD;
    float* Ss  = Vs + ATT_BC * ATT_PD;
    float* m_s = Ss + ATT_BR * ATT_PS;
    float* l_s = m_s + ATT_BR;
    float* sc_s = l_s + ATT_BR;

    int qt = gridDim.x - 1 - blockIdx.x;
    int bh = blockIdx.y;
    int tid = threadIdx.x;
    int ty = tid >> 4, tx = tid & 15;

    const float* Qg = g_q + ((size_t)bh * Sdim + (size_t)qt * ATT_BR) * Ddim;
    const float* Kg = g_k + (size_t)bh * Sdim * Ddim;
    const float* Vg = g_v + (size_t)bh * Sdim * Ddim;

    for (int i = tid * 4; i < ATT_BR * Ddim; i += 1024) {
        float4 v = *(const float4*)(Qg + i);
        int r = i >> 7, c = i & 127;
        float* q = Qs + r * ATT_PD + c;
        q[0] = v.x; q[1] = v.y; q[2] = v.z; q[3] = v.w;
    }
    if (tid < ATT_BR) { m_s[tid] = -INFINITY; l_s[tid] = 0.f; }

    float acc[4][8];
#pragma unroll
    for (int i = 0; i < 4; i++)
#pragma unroll
        for (int j = 0; j < 8; j++) acc[i][j] = 0.f;

    int nkt = 2 * qt + 2;
    for (int kt = 0; kt < nkt; kt++) {
        __syncthreads();
        const float* Kt = Kg + (size_t)kt * ATT_BC * Ddim;
        const float* Vt = Vg + (size_t)kt * ATT_BC * Ddim;
        for (int i = tid * 4; i < ATT_BC * Ddim; i += 1024) {
            float4 kv = *(const float4*)(Kt + i);
            float4 vv = *(const float4*)(Vt + i);
            int r = i >> 7, c = i & 127;
            float* kp = Ks + r * ATT_PD + c;
            kp[0] = kv.x; kp[1] = kv.y; kp[2] = kv.z; kp[3] = kv.w;
            float* vp = Vs + r * ATT_PD + c;
            vp[0] = vv.x; vp[1] = vv.y; vp[2] = vv.z; vp[3] = vv.w;
        }
        __syncthreads();

        float sa[4][2];
#pragma unroll
        for (int i = 0; i < 4; i++) { sa[i][0] = 0.f; sa[i][1] = 0.f; }
        const float* q0 = Qs + (ty * 4) * ATT_PD;
        const float* k0 = Ks + (tx * 2) * ATT_PD;
        for (int k = 0; k < Ddim; k += 4) {
            float4 b0 = *(const float4*)(k0 + k);
            float4 b1 = *(const float4*)(k0 + ATT_PD + k);
#pragma unroll
            for (int i = 0; i < 4; i++) {
                float4 a = *(const float4*)(q0 + i * ATT_PD + k);
                sa[i][0] += a.x * b0.x + a.y * b0.y + a.z * b0.z + a.w * b0.w;
                sa[i][1] += a.x * b1.x + a.y * b1.y + a.z * b1.z + a.w * b1.w;
            }
        }
        int qbase = qt * ATT_BR + ty * 4;
        int kbase = kt * ATT_BC + tx * 2;
#pragma unroll
        for (int i = 0; i < 4; i++) {
#pragma unroll
            for (int j = 0; j < 2; j++) {
                float v = sa[i][j] * 0.08838834764831845f;
                if (kbase + j > qbase + i) v = -1e30f;
                Ss[(ty * 4 + i) * ATT_PS + tx * 2 + j] = v;
            }
        }
        __syncthreads();

        if (tid < ATT_BR) {
            float mold = m_s[tid];
            float mnew = mold;
            float* srow = Ss + tid * ATT_PS;
#pragma unroll
            for (int c = 0; c < ATT_BC; c++) mnew = fmaxf(mnew, srow[c]);
            float lsum = 0.f;
#pragma unroll
            for (int c = 0; c < ATT_BC; c++) {
                float p = expf(srow[c] - mnew);
                srow[c] = p;
                lsum += p;
            }
            float scl = expf(mold - mnew);
            sc_s[tid] = scl;
            l_s[tid] = l_s[tid] * scl + lsum;
            m_s[tid] = mnew;
        }
        __syncthreads();

#pragma unroll
        for (int i = 0; i < 4; i++) {
            float scl = sc_s[ty * 4 + i];
#pragma unroll
            for (int j = 0; j < 8; j++) acc[i][j] *= scl;
        }
        const float* s0 = Ss + (ty * 4) * ATT_PS;
        const float* v0 = Vs + tx * 8;
        for (int c = 0; c < ATT_BC; c += 4) {
            float pr[4][4];
            *(float4*)pr[0] = *(const float4*)(s0 + 0 * ATT_PS + c);
            *(float4*)pr[1] = *(const float4*)(s0 + 1 * ATT_PS + c);
            *(float4*)pr[2] = *(const float4*)(s0 + 2 * ATT_PS + c);
            *(float4*)pr[3] = *(const float4*)(s0 + 3 * ATT_PS + c);
#pragma unroll
            for (int cc = 0; cc < 4; cc++) {
                float4 va = *(const float4*)(v0 + (c + cc) * ATT_PD);
                float4 vb = *(const float4*)(v0 + (c + cc) * ATT_PD + 4);
#pragma unroll
                for (int i = 0; i < 4; i++) {
                    float p = pr[i][cc];
                    acc[i][0] = fmaf(p, va.x, acc[i][0]);
                    acc[i][1] = fmaf(p, va.y, acc[i][1]);
                    acc[i][2] = fmaf(p, va.z, acc[i][2]);
                    acc[i][3] = fmaf(p, va.w, acc[i][3]);
                    acc[i][4] = fmaf(p, vb.x, acc[i][4]);
                    acc[i][5] = fmaf(p, vb.y, acc[i][5]);
                    acc[i][6] = fmaf(p, vb.z, acc[i][6]);
                    acc[i][7] = fmaf(p, vb.w, acc[i][7]);
                }
            }
        }
    }

    // write ctx as fp16 hi/lo in [B,S,H]
    int b = bh >> 4, h = bh & 15;
#pragma unroll
    for (int i = 0; i < 4; i++) {
        int r = ty * 4 + i;
        int sg = qt * ATT_BR + r;
        float inv = 1.0f / l_s[r];
        size_t off = ((size_t)(b * Sdim + sg) * Hdim) + h * Ddim + tx * 8;
#pragma unroll
        for (int j = 0; j < 8; j += 2) {
            float a0 = acc[i][j] * inv, a1 = acc[i][j + 1] * inv;
            __half2 hh, ll;
            split2(a0, a1, hh, ll);
            *(__half2*)(g_ctxh + off + j) = hh;
            *(__half2*)(g_ctxl + off + j) = ll;
        }
    }
}

// ============================ mask passthrough ============================
__global__ void mask_kernel(const unsigned char* __restrict__ m, float* __restrict__ o, int n) {
    int i = blockIdx.x * blockDim.x + threadIdx.x;
    if (i < n) o[i] = m[i] ? 1.0f : 0.0f;
}

// ============================ launch ============================
extern "C" void kernel_launch(void* const* d_in, const int* in_sizes, int n_in,
                              void* d_out, int out_size) {
    const float* hs            = (const float*)d_in[0];
    const unsigned char* mask  = (const unsigned char*)d_in[1];
    const float* ln1w          = (const float*)d_in[2];
    const float* ln1b          = (const float*)d_in[3];
    const float* wqkv          = (const float*)d_in[4];
    const float* bqkv          = (const float*)d_in[5];
    const float* wdense        = (const float*)d_in[6];
    const float* bdense        = (const float*)d_in[7];
    const float* ln2w          = (const float*)d_in[8];
    const float* ln2b          = (const float*)d_in[9];
    const float* w1            = (const float*)d_in[10];
    const float* b1            = (const float*)d_in[11];
    const float* w2            = (const float*)d_in[12];
    const float* b2            = (const float*)d_in[13];
    float* out = (float*)d_out;

    float *pqkv, *phid;
    __half *pxh, *pxl, *pctxh, *pctxl, *pinterh, *pinterl;
    __half *pwqkvh, *pwqkvl, *pwdh, *pw1h, *pw2h;
    cudaGetSymbolAddress((void**)&pqkv,   g_qkv);
    cudaGetSymbolAddress((void**)&phid,   g_hidden);
    cudaGetSymbolAddress((void**)&pxh,    g_xh);
    cudaGetSymbolAddress((void**)&pxl,    g_xl);
    cudaGetSymbolAddress((void**)&pctxh,  g_ctxh);
    cudaGetSymbolAddress((void**)&pctxl,  g_ctxl);
    cudaGetSymbolAddress((void**)&pinterh, g_interh);
    cudaGetSymbolAddress((void**)&pinterl, g_interl);
    cudaGetSymbolAddress((void**)&pwqkvh, g_wqkvh);
    cudaGetSymbolAddress((void**)&pwqkvl, g_wqkvl);
    cudaGetSymbolAddress((void**)&pwdh,   g_wdh);
    cudaGetSymbolAddress((void**)&pw1h,   g_w1h);
    cudaGetSymbolAddress((void**)&pw2h,   g_w2h);

    cudaFuncSetAttribute(attn_kernel, cudaFuncAttributeMaxDynamicSharedMemorySize,
                         ATTN_SMEM_BYTES);
    cudaFuncSetAttribute((hgemm<0,3>), cudaFuncAttributeMaxDynamicSharedMemorySize, HM_SMEM3);
    cudaFuncSetAttribute((hgemm<1,2>), cudaFuncAttributeMaxDynamicSharedMemorySize, HM_SMEM2);
    cudaFuncSetAttribute((hgemm<2,2>), cudaFuncAttributeMaxDynamicSharedMemorySize, HM_SMEM2);

    // weight prep: QKV hi+lo (3-pass); dense/w1/w2 hi only (2-pass)
    split_kernel<<<(3*Hdim*Hdim/2 + 255)/256, 256>>>(wqkv, pwqkvh, pwqkvl, 3*Hdim*Hdim/2);
    cvt_kernel<<<(Hdim*Hdim/2  + 255)/256, 256>>>(wdense, pwdh, Hdim*Hdim/2);
    cvt_kernel<<<(FFdim*Hdim/2 + 255)/256, 256>>>(w1,     pw1h, FFdim*Hdim/2);
    cvt_kernel<<<(Hdim*FFdim/2 + 255)/256, 256>>>(w2,     pw2h, Hdim*FFdim/2);
    // LN1 -> xh/xl
    ln_kernel<<<Mrows, 256>>>(hs, ln1w, ln1b, pxh, pxl);
    // RoPE trig table
    rope_table_kernel<<<(Sdim * 64) / 256, 256>>>();
    // QKV = x @ wqkv^T + bqkv (3-pass, fp32 out for rope)
    hgemm<0,3><<<dim3(3 * Hdim / GBN, Mrows / GBM), 512, HM_SMEM3>>>(
        pxh, pxl, pwqkvh, pwqkvl, bqkv, nullptr, pqkv, nullptr, nullptr,
        Mrows, 3 * Hdim, Hdim);
    // split + rope -> g_q, g_k, g_v in [B,NH,S,D]
    rope_kernel<<<dim3(Mrows, NHdim), 128>>>();
    // flash attention -> ctxh/ctxl in [B,S,H]
    attn_kernel<<<dim3(Sdim / ATT_BR, Bdim * NHdim), 256, ATTN_SMEM_BYTES>>>();
    // dense + residual(hidden_states) -> g_hidden (2-pass)
    hgemm<2,2><<<dim3(Hdim / GBN, Mrows / GBM), 512, HM_SMEM2>>>(
        pctxh, pctxl, pwdh, nullptr, bdense, hs, phid, nullptr, nullptr,
        Mrows, Hdim, Hdim);
    // LN2 -> xh/xl
    ln_kernel<<<Mrows, 256>>>(phid, ln2w, ln2b, pxh, pxl);
    // FF1 + GELU -> interh/interl (2-pass)
    hgemm<1,2><<<dim3(FFdim / GBN, Mrows / GBM), 512, HM_SMEM2>>>(
        pxh, pxl, pw1h, nullptr, b1, nullptr, nullptr, pinterh, pinterl,
        Mrows, FFdim, Hdim);
    // FF2 + residual(g_hidden) -> out (2-pass)
    hgemm<2,2><<<dim3(Hdim / GBN, Mrows / GBM), 512, HM_SMEM2>>>(
        pinterh, pinterl, pw2h, nullptr, b2, phid, out, nullptr, nullptr,
        Mrows, Hdim, FFdim);
    // if output also carries the attention mask, convert it after hidden
    long long hid_elems = (long long)Mrows * Hdim;           // 8388608
    long long mask_elems = (long long)Sdim * Sdim;           // 4194304
    if ((long long)out_size >= hid_elems + mask_elems) {
        mask_kernel<<<(int)(mask_elems / 256), 256>>>(mask, out + hid_elems, (int)mask_elems);
    }
}

// round 9
// speedup vs baseline: 1.8668x; 1.5595x over previous
#include <cuda_runtime.h>
#include <cuda_fp16.h>
#include <cstdint>
#include <stdint.h>
#include <math.h>

// Problem constants
#define Bdim 2
#define Sdim 2048
#define Hdim 2048
#define NHdim 16
#define Ddim 128
#define FFdim 8192
#define Mrows (Bdim*Sdim)   // 4096

// -------- scratch (device globals; no allocation) --------
__device__ float g_qkv[(size_t)Mrows*3*Hdim];    // QKV gemm out (fp32, for rope)
__device__ float g_q[(size_t)Mrows*Hdim];        // [B,NH,S,D]
__device__ float g_k[(size_t)Mrows*Hdim];
__device__ float g_v[(size_t)Mrows*Hdim];
__device__ float g_hidden[(size_t)Mrows*Hdim];   // residual+attn_out
__device__ float g_cos[Sdim*64];
__device__ float g_sin[Sdim*64];
// fp16 operand arrays (single precision-level, 1-pass GEMM)
__device__ __half g_xh[(size_t)Mrows*Hdim];
__device__ __half g_ctxh[(size_t)Mrows*Hdim];
__device__ __half g_interh[(size_t)Mrows*FFdim];
__device__ __half g_wqkvh[(size_t)3*Hdim*Hdim];
__device__ __half g_wdh[(size_t)Hdim*Hdim];
__device__ __half g_w1h[(size_t)FFdim*Hdim];
__device__ __half g_w2h[(size_t)Hdim*FFdim];

// ============================ helpers ============================
__device__ __forceinline__ uint32_t smem_u32(const void* p) {
    uint32_t a;
    asm("{ .reg .u64 t; cvta.to.shared.u64 t, %1; cvt.u32.u64 %0, t; }" : "=r"(a) : "l"(p));
    return a;
}
__device__ __forceinline__ void ldsm4(uint32_t* r, uint32_t addr) {
    asm volatile("ldmatrix.sync.aligned.m8n8.x4.shared.b16 {%0,%1,%2,%3}, [%4];"
        : "=r"(r[0]), "=r"(r[1]), "=r"(r[2]), "=r"(r[3]) : "r"(addr));
}
__device__ __forceinline__ void mma16816(float* c, const uint32_t* a, uint32_t b0, uint32_t b1) {
    asm("mma.sync.aligned.m16n8k16.row.col.f32.f16.f16.f32 "
        "{%0,%1,%2,%3}, {%4,%5,%6,%7}, {%8,%9}, {%0,%1,%2,%3};"
        : "+f"(c[0]), "+f"(c[1]), "+f"(c[2]), "+f"(c[3])
        : "r"(a[0]), "r"(a[1]), "r"(a[2]), "r"(a[3]), "r"(b0), "r"(b1));
}
__device__ __forceinline__ void cp16(uint32_t dst, const void* src) {
    asm volatile("cp.async.cg.shared.global [%0], [%1], 16;"
        :: "r"(dst), "l"(__cvta_generic_to_global(src)) : "memory");
}
#define CP_COMMIT() asm volatile("cp.async.commit_group;" ::: "memory")
#define CP_WAIT(n)  asm volatile("cp.async.wait_group %0;" :: "n"(n) : "memory")

// swizzled smem offset: rows of 64B (32 halfs), 16B chunk XOR (row>>1)&3
__device__ __forceinline__ uint32_t swoff(int row, int chunk) {
    return (uint32_t)(row * 64 + ((chunk ^ ((row >> 1) & 3)) << 4));
}

// ============================ weight convert kernel ============================
__global__ void cvt_kernel(const float* __restrict__ in, __half* __restrict__ hi, int n2) {
    int i = blockIdx.x * blockDim.x + threadIdx.x;
    if (i >= n2) return;
    float2 v = *(const float2*)(in + (size_t)i * 2);
    *(__half2*)(hi + (size_t)i * 2) = __floats2half2_rn(v.x, v.y);
}

// ============================ HMMA GEMM v6 (1-pass fp16, 256x128 tile) ============================
// A: [M,K] half, W: [N,K] half, fp32 accumulate.
// EPI: 0 = bias -> C fp32 ; 1 = bias+GELU -> Ch half ; 2 = bias+residual -> C fp32
#define GBM 256
#define GBN 128
#define NSTAGE 3
#define STAGE1 24576     // Ah 16K | Wh 8K
#define HM_SMEM (NSTAGE*STAGE1)

template<int EPI>
__global__ void __launch_bounds__(512, 1) hgemm(
    const __half* __restrict__ Ah_, const __half* __restrict__ Wh_,
    const float* __restrict__ bias, const float* __restrict__ res,
    float* __restrict__ C, __half* __restrict__ Ch,
    int M, int N, int K)
{
    extern __shared__ char sm[];
    uint32_t smb = smem_u32(sm);
    int tid = threadIdx.x;
    int lane = tid & 31, wid = tid >> 5;
    int wm = (wid & 3) * 64;       // 4 warp-rows over 256
    int wn = (wid >> 2) * 32;      // 4 warp-cols over 128
    int bm = blockIdx.y * GBM, bn = blockIdx.x * GBN;

    // loader coords: A -> 1024 chunk-slots (256 rows x 4 chunks), 2 per thread (same row)
    int aidx = tid * 2;
    int arow = aidx >> 2, ach = aidx & 3;
    // W -> 512 chunk-slots (128 rows x 4 chunks), 1 per thread
    int wrow = tid >> 2, wch = tid & 3;
    const __half* pAh = Ah_ + (size_t)(bm + arow) * K + ach * 8;
    const __half* pWh = Wh_ + (size_t)(bn + wrow) * K + wch * 8;
    uint32_t dA0 = swoff(arow, ach), dA1 = swoff(arow, ach + 1);
    uint32_t dW  = swoff(wrow, wch);

    float acc[4][4][4];
#pragma unroll
    for (int i = 0; i < 4; i++)
#pragma unroll
        for (int j = 0; j < 4; j++)
#pragma unroll
            for (int q = 0; q < 4; q++) acc[i][j][q] = 0.f;

    int mat = lane >> 3, mr = lane & 7;
    int fr_row = (mat & 1) * 8 + mr;
    int fr_ch  = mat >> 1;

    const int NC = K >> 5;

    auto load_stage = [&](int c) {
        uint32_t base = smb + (uint32_t)(c % NSTAGE) * STAGE1;
        size_t ko = (size_t)c * 32;
        cp16(base + 0     + dA0, pAh + ko);
        cp16(base + 0     + dA1, pAh + ko + 8);
        cp16(base + 16384 + dW,  pWh + ko);
    };

    // prologue: 2 stages in flight
#pragma unroll
    for (int c = 0; c < NSTAGE - 1; c++) { load_stage(c); CP_COMMIT(); }

    for (int c = 0; c < NC; c++) {
        CP_WAIT(NSTAGE - 2);
        __syncthreads();
        if (c + NSTAGE - 1 < NC) { load_stage(c + NSTAGE - 1); }
        CP_COMMIT();

        uint32_t base = smb + (uint32_t)(c % NSTAGE) * STAGE1;
#pragma unroll
        for (int kk = 0; kk < 2; kk++) {
            uint32_t ah[4][4], bh[2][4];
#pragma unroll
            for (int i = 0; i < 4; i++) {
                uint32_t off = swoff(wm + i * 16 + fr_row, kk * 2 + fr_ch);
                ldsm4(ah[i], base + 0 + off);
            }
#pragma unroll
            for (int g = 0; g < 2; g++) {
                uint32_t off = swoff(wn + g * 16 + fr_row, kk * 2 + fr_ch);
                ldsm4(bh[g], base + 16384 + off);
            }
#pragma unroll
            for (int i = 0; i < 4; i++) {
#pragma unroll
                for (int jj = 0; jj < 4; jj++) {
                    int g = jj >> 1, h = jj & 1;
                    mma16816(acc[i][jj], ah[i], bh[g][h], bh[g][h+2]);
                }
            }
        }
    }

    // epilogue
    int tr = lane >> 2;
    int tc = (lane & 3) * 2;
#pragma unroll
    for (int i = 0; i < 4; i++) {
#pragma unroll
        for (int jj = 0; jj < 4; jj++) {
            int n0 = bn + wn + jj * 8 + tc;
            float b0 = bias[n0], b1 = bias[n0 + 1];
#pragma unroll
            for (int half = 0; half < 2; half++) {
                int m = bm + wm + i * 16 + tr + half * 8;
                size_t idx = (size_t)m * N + n0;
                float v0 = acc[i][jj][half * 2 + 0] + b0;
                float v1 = acc[i][jj][half * 2 + 1] + b1;
                if (EPI == 1) {
                    v0 = 0.5f * v0 * (1.0f + erff(v0 * 0.70710678118654752f));
                    v1 = 0.5f * v1 * (1.0f + erff(v1 * 0.70710678118654752f));
                    *(__half2*)(Ch + idx) = __floats2half2_rn(v0, v1);
                } else {
                    if (EPI == 2) { v0 += res[idx]; v1 += res[idx + 1]; }
                    *(float2*)(C + idx) = make_float2(v0, v1);
                }
            }
        }
    }
}

// ============================ LayerNorm -> fp16 ============================
__global__ void ln_kernel(const float* __restrict__ in, const float* __restrict__ w,
                          const float* __restrict__ b, __half* __restrict__ oh) {
    __shared__ float2 red[256];
    int row = blockIdx.x;
    const float* x = in + (size_t)row * Hdim;
    float s = 0.f, ss = 0.f;
    for (int i = threadIdx.x * 2; i < Hdim; i += 512) {
        float2 v = *(const float2*)(x + i);
        s += v.x + v.y;
        ss = fmaf(v.x, v.x, fmaf(v.y, v.y, ss));
    }
    red[threadIdx.x] = make_float2(s, ss);
    __syncthreads();
    for (int o = 128; o > 0; o >>= 1) {
        if (threadIdx.x < o) {
            float2 a = red[threadIdx.x], c = red[threadIdx.x + o];
            red[threadIdx.x] = make_float2(a.x + c.x, a.y + c.y);
        }
        __syncthreads();
    }
    float mean = red[0].x * (1.0f / Hdim);
    float var  = red[0].y * (1.0f / Hdim) - mean * mean;
    float rstd = rsqrtf(var + 1e-5f);
    for (int i = threadIdx.x * 2; i < Hdim; i += 512) {
        float2 v = *(const float2*)(x + i);
        float2 wv = *(const float2*)(w + i);
        float2 bv = *(const float2*)(b + i);
        float o0 = (v.x - mean) * rstd * wv.x + bv.x;
        float o1 = (v.y - mean) * rstd * wv.y + bv.y;
        *(__half2*)(oh + (size_t)row * Hdim + i) = __floats2half2_rn(o0, o1);
    }
}

// ============================ RoPE table (double precision trig) ============================
__global__ void rope_table_kernel() {
    int idx = blockIdx.x * blockDim.x + threadIdx.x;
    if (idx >= Sdim * 64) return;
    int s = idx >> 6, i = idx & 63;
    double invf = exp(-(double)i * (9.210340371976184 / 64.0)); // ln(10000)/64
    double th = (double)s * invf;
    g_cos[idx] = (float)cos(th);
    g_sin[idx] = (float)sin(th);
}

// ============================ QKV split + RoPE ============================
__global__ void rope_kernel() {
    int row = blockIdx.x;      // b*S + s
    int h = blockIdx.y;
    int d = threadIdx.x;       // 0..127
    int s = row & (Sdim - 1);
    int b = row >> 11;
    const float* src = g_qkv + (size_t)row * (3 * Hdim) + h * (3 * Ddim);
    float q = src[d];
    float k = src[Ddim + d];
    float v = src[2 * Ddim + d];
    int di = d & 63;
    float cs = g_cos[s * 64 + di];
    float sn = g_sin[s * 64 + di];
    float qp, kp;
    if (d < 64) { qp = -src[d + 64];        kp = -src[Ddim + d + 64]; }
    else        { qp =  src[d - 64];        kp =  src[Ddim + d - 64]; }
    size_t oidx = ((size_t)(b * NHdim + h) * Sdim + s) * Ddim + d;
    g_q[oidx] = q * cs + qp * sn;
    g_k[oidx] = k * cs + kp * sn;
    g_v[oidx] = v;
}

// ============================ Flash attention (fp32, causal) ============================
#define ATT_BR 64
#define ATT_BC 32
#define ATT_PD 132
#define ATT_PS 36
#define ATTN_SMEM_BYTES ((ATT_BR*ATT_PD + 2*ATT_BC*ATT_PD + ATT_BR*ATT_PS + 3*ATT_BR) * 4)

__global__ void __launch_bounds__(256) attn_kernel() {
    extern __shared__ float smf[];
    float* Qs  = smf;
    float* Ks  = Qs + ATT_BR * ATT_PD;
    float* Vs  = Ks + ATT_BC * ATT_PD;
    float* Ss  = Vs + ATT_BC * ATT_PD;
    float* m_s = Ss + ATT_BR * ATT_PS;
    float* l_s = m_s + ATT_BR;
    float* sc_s = l_s + ATT_BR;

    int qt = gridDim.x - 1 - blockIdx.x;
    int bh = blockIdx.y;
    int tid = threadIdx.x;
    int ty = tid >> 4, tx = tid & 15;

    const float* Qg = g_q + ((size_t)bh * Sdim + (size_t)qt * ATT_BR) * Ddim;
    const float* Kg = g_k + (size_t)bh * Sdim * Ddim;
    const float* Vg = g_v + (size_t)bh * Sdim * Ddim;

    for (int i = tid * 4; i < ATT_BR * Ddim; i += 1024) {
        float4 v = *(const float4*)(Qg + i);
        int r = i >> 7, c = i & 127;
        float* q = Qs + r * ATT_PD + c;
        q[0] = v.x; q[1] = v.y; q[2] = v.z; q[3] = v.w;
    }
    if (tid < ATT_BR) { m_s[tid] = -INFINITY; l_s[tid] = 0.f; }

    float acc[4][8];
#pragma unroll
    for (int i = 0; i < 4; i++)
#pragma unroll
        for (int j = 0; j < 8; j++) acc[i][j] = 0.f;

    int nkt = 2 * qt + 2;
    for (int kt = 0; kt < nkt; kt++) {
        __syncthreads();
        const float* Kt = Kg + (size_t)kt * ATT_BC * Ddim;
        const float* Vt = Vg + (size_t)kt * ATT_BC * Ddim;
        for (int i = tid * 4; i < ATT_BC * Ddim; i += 1024) {
            float4 kv = *(const float4*)(Kt + i);
            float4 vv = *(const float4*)(Vt + i);
            int r = i >> 7, c = i & 127;
            float* kp = Ks + r * ATT_PD + c;
            kp[0] = kv.x; kp[1] = kv.y; kp[2] = kv.z; kp[3] = kv.w;
            float* vp = Vs + r * ATT_PD + c;
            vp[0] = vv.x; vp[1] = vv.y; vp[2] = vv.z; vp[3] = vv.w;
        }
        __syncthreads();

        float sa[4][2];
#pragma unroll
        for (int i = 0; i < 4; i++) { sa[i][0] = 0.f; sa[i][1] = 0.f; }
        const float* q0 = Qs + (ty * 4) * ATT_PD;
        const float* k0 = Ks + (tx * 2) * ATT_PD;
        for (int k = 0; k < Ddim; k += 4) {
            float4 b0 = *(const float4*)(k0 + k);
            float4 b1 = *(const float4*)(k0 + ATT_PD + k);
#pragma unroll
            for (int i = 0; i < 4; i++) {
                float4 a = *(const float4*)(q0 + i * ATT_PD + k);
                sa[i][0] += a.x * b0.x + a.y * b0.y + a.z * b0.z + a.w * b0.w;
                sa[i][1] += a.x * b1.x + a.y * b1.y + a.z * b1.z + a.w * b1.w;
            }
        }
        int qbase = qt * ATT_BR + ty * 4;
        int kbase = kt * ATT_BC + tx * 2;
#pragma unroll
        for (int i = 0; i < 4; i++) {
#pragma unroll
            for (int j = 0; j < 2; j++) {
                float v = sa[i][j] * 0.08838834764831845f;
                if (kbase + j > qbase + i) v = -1e30f;
                Ss[(ty * 4 + i) * ATT_PS + tx * 2 + j] = v;
            }
        }
        __syncthreads();

        if (tid < ATT_BR) {
            float mold = m_s[tid];
            float mnew = mold;
            float* srow = Ss + tid * ATT_PS;
#pragma unroll
            for (int c = 0; c < ATT_BC; c++) mnew = fmaxf(mnew, srow[c]);
            float lsum = 0.f;
#pragma unroll
            for (int c = 0; c < ATT_BC; c++) {
                float p = expf(srow[c] - mnew);
                srow[c] = p;
                lsum += p;
            }
            float scl = expf(mold - mnew);
            sc_s[tid] = scl;
            l_s[tid] = l_s[tid] * scl + lsum;
            m_s[tid] = mnew;
        }
        __syncthreads();

#pragma unroll
        for (int i = 0; i < 4; i++) {
            float scl = sc_s[ty * 4 + i];
#pragma unroll
            for (int j = 0; j < 8; j++) acc[i][j] *= scl;
        }
        const float* s0 = Ss + (ty * 4) * ATT_PS;
        const float* v0 = Vs + tx * 8;
        for (int c = 0; c < ATT_BC; c += 4) {
            float pr[4][4];
            *(float4*)pr[0] = *(const float4*)(s0 + 0 * ATT_PS + c);
            *(float4*)pr[1] = *(const float4*)(s0 + 1 * ATT_PS + c);
            *(float4*)pr[2] = *(const float4*)(s0 + 2 * ATT_PS + c);
            *(float4*)pr[3] = *(const float4*)(s0 + 3 * ATT_PS + c);
#pragma unroll
            for (int cc = 0; cc < 4; cc++) {
                float4 va = *(const float4*)(v0 + (c + cc) * ATT_PD);
                float4 vb = *(const float4*)(v0 + (c + cc) * ATT_PD + 4);
#pragma unroll
                for (int i = 0; i < 4; i++) {
                    float p = pr[i][cc];
                    acc[i][0] = fmaf(p, va.x, acc[i][0]);
                    acc[i][1] = fmaf(p, va.y, acc[i][1]);
                    acc[i][2] = fmaf(p, va.z, acc[i][2]);
                    acc[i][3] = fmaf(p, va.w, acc[i][3]);
                    acc[i][4] = fmaf(p, vb.x, acc[i][4]);
                    acc[i][5] = fmaf(p, vb.y, acc[i][5]);
                    acc[i][6] = fmaf(p, vb.z, acc[i][6]);
                    acc[i][7] = fmaf(p, vb.w, acc[i][7]);
                }
            }
        }
    }

    // write ctx as fp16 in [B,S,H]
    int b = bh >> 4, h = bh & 15;
#pragma unroll
    for (int i = 0; i < 4; i++) {
        int r = ty * 4 + i;
        int sg = qt * ATT_BR + r;
        float inv = 1.0f / l_s[r];
        size_t off = ((size_t)(b * Sdim + sg) * Hdim) + h * Ddim + tx * 8;
#pragma unroll
        for (int j = 0; j < 8; j += 2) {
            *(__half2*)(g_ctxh + off + j) =
                __floats2half2_rn(acc[i][j] * inv, acc[i][j + 1] * inv);
        }
    }
}

// ============================ mask passthrough ============================
__global__ void mask_kernel(const unsigned char* __restrict__ m, float* __restrict__ o, int n) {
    int i = blockIdx.x * blockDim.x + threadIdx.x;
    if (i < n) o[i] = m[i] ? 1.0f : 0.0f;
}

// ============================ launch ============================
extern "C" void kernel_launch(void* const* d_in, const int* in_sizes, int n_in,
                              void* d_out, int out_size) {
    const float* hs            = (const float*)d_in[0];
    const unsigned char* mask  = (const unsigned char*)d_in[1];
    const float* ln1w          = (const float*)d_in[2];
    const float* ln1b          = (const float*)d_in[3];
    const float* wqkv          = (const float*)d_in[4];
    const float* bqkv          = (const float*)d_in[5];
    const float* wdense        = (const float*)d_in[6];
    const float* bdense        = (const float*)d_in[7];
    const float* ln2w          = (const float*)d_in[8];
    const float* ln2b          = (const float*)d_in[9];
    const float* w1            = (const float*)d_in[10];
    const float* b1            = (const float*)d_in[11];
    const float* w2            = (const float*)d_in[12];
    const float* b2            = (const float*)d_in[13];
    float* out = (float*)d_out;

    float *pqkv, *phid;
    __half *pxh, *pctxh, *pinterh, *pwqkvh, *pwdh, *pw1h, *pw2h;
    cudaGetSymbolAddress((void**)&pqkv,   g_qkv);
    cudaGetSymbolAddress((void**)&phid,   g_hidden);
    cudaGetSymbolAddress((void**)&pxh,    g_xh);
    cudaGetSymbolAddress((void**)&pctxh,  g_ctxh);
    cudaGetSymbolAddress((void**)&pinterh, g_interh);
    cudaGetSymbolAddress((void**)&pwqkvh, g_wqkvh);
    cudaGetSymbolAddress((void**)&pwdh,   g_wdh);
    cudaGetSymbolAddress((void**)&pw1h,   g_w1h);
    cudaGetSymbolAddress((void**)&pw2h,   g_w2h);

    cudaFuncSetAttribute(attn_kernel, cudaFuncAttributeMaxDynamicSharedMemorySize,
                         ATTN_SMEM_BYTES);
    cudaFuncSetAttribute(hgemm<0>, cudaFuncAttributeMaxDynamicSharedMemorySize, HM_SMEM);
    cudaFuncSetAttribute(hgemm<1>, cudaFuncAttributeMaxDynamicSharedMemorySize, HM_SMEM);
    cudaFuncSetAttribute(hgemm<2>, cudaFuncAttributeMaxDynamicSharedMemorySize, HM_SMEM);

    // weight prep: fp32 -> fp16 (all single precision level)
    cvt_kernel<<<(3*Hdim*Hdim/2 + 255)/256, 256>>>(wqkv, pwqkvh, 3*Hdim*Hdim/2);
    cvt_kernel<<<(Hdim*Hdim/2   + 255)/256, 256>>>(wdense, pwdh, Hdim*Hdim/2);
    cvt_kernel<<<(FFdim*Hdim/2  + 255)/256, 256>>>(w1,     pw1h, FFdim*Hdim/2);
    cvt_kernel<<<(Hdim*FFdim/2  + 255)/256, 256>>>(w2,     pw2h, Hdim*FFdim/2);
    // LN1 -> xh
    ln_kernel<<<Mrows, 256>>>(hs, ln1w, ln1b, pxh);
    // RoPE trig table
    rope_table_kernel<<<(Sdim * 64) / 256, 256>>>();
    // QKV = x @ wqkv^T + bqkv (fp32 out for rope)
    hgemm<0><<<dim3(3 * Hdim / GBN, Mrows / GBM), 512, HM_SMEM>>>(
        pxh, pwqkvh, bqkv, nullptr, pqkv, nullptr, Mrows, 3 * Hdim, Hdim);
    // split + rope -> g_q, g_k, g_v in [B,NH,S,D]
    rope_kernel<<<dim3(Mrows, NHdim), 128>>>();
    // flash attention -> ctxh in [B,S,H]
    attn_kernel<<<dim3(Sdim / ATT_BR, Bdim * NHdim), 256, ATTN_SMEM_BYTES>>>();
    // dense + residual(hidden_states) -> g_hidden (fp32)
    hgemm<2><<<dim3(Hdim / GBN, Mrows / GBM), 512, HM_SMEM>>>(
        pctxh, pwdh, bdense, hs, phid, nullptr, Mrows, Hdim, Hdim);
    // LN2 -> xh
    ln_kernel<<<Mrows, 256>>>(phid, ln2w, ln2b, pxh);
    // FF1 + GELU -> interh (fp16)
    hgemm<1><<<dim3(FFdim / GBN, Mrows / GBM), 512, HM_SMEM>>>(
        pxh, pw1h, b1, nullptr, nullptr, pinterh, Mrows, FFdim, Hdim);
    // FF2 + residual(g_hidden) -> out
    hgemm<2><<<dim3(Hdim / GBN, Mrows / GBM), 512, HM_SMEM>>>(
        pinterh, pw2h, b2, phid, out, nullptr, Mrows, Hdim, FFdim);
    // if output also carries the attention mask, convert it after hidden
    long long hid_elems = (long long)Mrows * Hdim;           // 8388608
    long long mask_elems = (long long)Sdim * Sdim;           // 4194304
    if ((long long)out_size >= hid_elems + mask_elems) {
        mask_kernel<<<(int)(mask_elems / 256), 256>>>(mask, out + hid_elems, (int)mask_elems);
    }
}

// round 10
// speedup vs baseline: 3.3328x; 1.7853x over previous
#include <cuda_runtime.h>
#include <cuda_fp16.h>
#include <cstdint>
#include <stdint.h>
#include <math.h>

// Problem constants
#define Bdim 2
#define Sdim 2048
#define Hdim 2048
#define NHdim 16
#define Ddim 128
#define FFdim 8192
#define Mrows (Bdim*Sdim)   // 4096

// -------- scratch (device globals; no allocation) --------
__device__ float g_hidden[(size_t)Mrows*Hdim];   // residual+attn_out
__device__ float g_cos[Sdim*64];
__device__ float g_sin[Sdim*64];
__device__ __half g_qkvh[(size_t)Mrows*3*Hdim];  // QKV gemm out (half)
__device__ __half g_qh[(size_t)Mrows*Hdim];      // [B,NH,S,D]
__device__ __half g_kh[(size_t)Mrows*Hdim];
__device__ __half g_vh[(size_t)Mrows*Hdim];
__device__ __half g_vt[(size_t)Mrows*Hdim];      // [B,NH,D,S]
__device__ __half g_xh[(size_t)Mrows*Hdim];
__device__ __half g_ctxh[(size_t)Mrows*Hdim];
__device__ __half g_interh[(size_t)Mrows*FFdim];
__device__ __half g_wqkvh[(size_t)3*Hdim*Hdim];
__device__ __half g_wdh[(size_t)Hdim*Hdim];
__device__ __half g_w1h[(size_t)FFdim*Hdim];
__device__ __half g_w2h[(size_t)Hdim*FFdim];

// ============================ helpers ============================
__device__ __forceinline__ uint32_t smem_u32(const void* p) {
    uint32_t a;
    asm("{ .reg .u64 t; cvta.to.shared.u64 t, %1; cvt.u32.u64 %0, t; }" : "=r"(a) : "l"(p));
    return a;
}
__device__ __forceinline__ void ldsm4(uint32_t* r, uint32_t addr) {
    asm volatile("ldmatrix.sync.aligned.m8n8.x4.shared.b16 {%0,%1,%2,%3}, [%4];"
        : "=r"(r[0]), "=r"(r[1]), "=r"(r[2]), "=r"(r[3]) : "r"(addr));
}
__device__ __forceinline__ void mma16816(float* c, const uint32_t* a, uint32_t b0, uint32_t b1) {
    asm("mma.sync.aligned.m16n8k16.row.col.f32.f16.f16.f32 "
        "{%0,%1,%2,%3}, {%4,%5,%6,%7}, {%8,%9}, {%0,%1,%2,%3};"
        : "+f"(c[0]), "+f"(c[1]), "+f"(c[2]), "+f"(c[3])
        : "r"(a[0]), "r"(a[1]), "r"(a[2]), "r"(a[3]), "r"(b0), "r"(b1));
}
__device__ __forceinline__ void cp16(uint32_t dst, const void* src) {
    asm volatile("cp.async.cg.shared.global [%0], [%1], 16;"
        :: "r"(dst), "l"(__cvta_generic_to_global(src)) : "memory");
}
#define CP_COMMIT() asm volatile("cp.async.commit_group;" ::: "memory")
#define CP_WAIT(n)  asm volatile("cp.async.wait_group %0;" :: "n"(n) : "memory")

__device__ __forceinline__ float ex2(float x) {
    float r;
    asm("ex2.approx.ftz.f32 %0, %1;" : "=f"(r) : "f"(x));
    return r;
}
__device__ __forceinline__ uint32_t f22u(float a, float b) {
    __half2 h = __floats2half2_rn(a, b);
    return *(uint32_t*)&h;
}

// swizzled smem offset: rows of 64B (32 halfs), 16B chunk XOR (row>>1)&3
__device__ __forceinline__ uint32_t swoff(int row, int chunk) {
    return (uint32_t)(row * 64 + ((chunk ^ ((row >> 1) & 3)) << 4));
}

// ============================ weight convert kernel ============================
__global__ void cvt_kernel(const float* __restrict__ in, __half* __restrict__ hi, int n2) {
    int i = blockIdx.x * blockDim.x + threadIdx.x;
    if (i >= n2) return;
    float2 v = *(const float2*)(in + (size_t)i * 2);
    *(__half2*)(hi + (size_t)i * 2) = __floats2half2_rn(v.x, v.y);
}

// ============================ HMMA GEMM (1-pass fp16, 256x128 tile) ============================
// EPI: 0 = bias -> C fp32 ; 1 = bias+GELU -> Ch half ; 2 = bias+residual -> C fp32 ; 3 = bias -> Ch half
#define GBM 256
#define GBN 128
#define NSTAGE 3
#define STAGE1 24576     // Ah 16K | Wh 8K
#define HM_SMEM (NSTAGE*STAGE1)

template<int EPI>
__global__ void __launch_bounds__(512, 1) hgemm(
    const __half* __restrict__ Ah_, const __half* __restrict__ Wh_,
    const float* __restrict__ bias, const float* __restrict__ res,
    float* __restrict__ C, __half* __restrict__ Ch,
    int M, int N, int K)
{
    extern __shared__ char sm[];
    uint32_t smb = smem_u32(sm);
    int tid = threadIdx.x;
    int lane = tid & 31, wid = tid >> 5;
    int wm = (wid & 3) * 64;
    int wn = (wid >> 2) * 32;
    int bm = blockIdx.y * GBM, bn = blockIdx.x * GBN;

    int aidx = tid * 2;
    int arow = aidx >> 2, ach = aidx & 3;
    int wrow = tid >> 2, wch = tid & 3;
    const __half* pAh = Ah_ + (size_t)(bm + arow) * K + ach * 8;
    const __half* pWh = Wh_ + (size_t)(bn + wrow) * K + wch * 8;
    uint32_t dA0 = swoff(arow, ach), dA1 = swoff(arow, ach + 1);
    uint32_t dW  = swoff(wrow, wch);

    float acc[4][4][4];
#pragma unroll
    for (int i = 0; i < 4; i++)
#pragma unroll
        for (int j = 0; j < 4; j++)
#pragma unroll
            for (int q = 0; q < 4; q++) acc[i][j][q] = 0.f;

    int mat = lane >> 3, mr = lane & 7;
    int fr_row = (mat & 1) * 8 + mr;
    int fr_ch  = mat >> 1;

    const int NC = K >> 5;

    auto load_stage = [&](int c) {
        uint32_t base = smb + (uint32_t)(c % NSTAGE) * STAGE1;
        size_t ko = (size_t)c * 32;
        cp16(base + 0     + dA0, pAh + ko);
        cp16(base + 0     + dA1, pAh + ko + 8);
        cp16(base + 16384 + dW,  pWh + ko);
    };

#pragma unroll
    for (int c = 0; c < NSTAGE - 1; c++) { load_stage(c); CP_COMMIT(); }

    for (int c = 0; c < NC; c++) {
        CP_WAIT(NSTAGE - 2);
        __syncthreads();
        if (c + NSTAGE - 1 < NC) { load_stage(c + NSTAGE - 1); }
        CP_COMMIT();

        uint32_t base = smb + (uint32_t)(c % NSTAGE) * STAGE1;
#pragma unroll
        for (int kk = 0; kk < 2; kk++) {
            uint32_t ah[4][4], bh[2][4];
#pragma unroll
            for (int i = 0; i < 4; i++) {
                uint32_t off = swoff(wm + i * 16 + fr_row, kk * 2 + fr_ch);
                ldsm4(ah[i], base + 0 + off);
            }
#pragma unroll
            for (int g = 0; g < 2; g++) {
                uint32_t off = swoff(wn + g * 16 + fr_row, kk * 2 + fr_ch);
                ldsm4(bh[g], base + 16384 + off);
            }
#pragma unroll
            for (int i = 0; i < 4; i++) {
#pragma unroll
                for (int jj = 0; jj < 4; jj++) {
                    int g = jj >> 1, h = jj & 1;
                    mma16816(acc[i][jj], ah[i], bh[g][h], bh[g][h+2]);
                }
            }
        }
    }

    int tr = lane >> 2;
    int tc = (lane & 3) * 2;
#pragma unroll
    for (int i = 0; i < 4; i++) {
#pragma unroll
        for (int jj = 0; jj < 4; jj++) {
            int n0 = bn + wn + jj * 8 + tc;
            float b0 = bias[n0], b1 = bias[n0 + 1];
#pragma unroll
            for (int half = 0; half < 2; half++) {
                int m = bm + wm + i * 16 + tr + half * 8;
                size_t idx = (size_t)m * N + n0;
                float v0 = acc[i][jj][half * 2 + 0] + b0;
                float v1 = acc[i][jj][half * 2 + 1] + b1;
                if (EPI == 1) {
                    v0 = 0.5f * v0 * (1.0f + erff(v0 * 0.70710678118654752f));
                    v1 = 0.5f * v1 * (1.0f + erff(v1 * 0.70710678118654752f));
                    *(__half2*)(Ch + idx) = __floats2half2_rn(v0, v1);
                } else if (EPI == 3) {
                    *(__half2*)(Ch + idx) = __floats2half2_rn(v0, v1);
                } else {
                    if (EPI == 2) { v0 += res[idx]; v1 += res[idx + 1]; }
                    *(float2*)(C + idx) = make_float2(v0, v1);
                }
            }
        }
    }
}

// ============================ LayerNorm -> fp16 ============================
__global__ void ln_kernel(const float* __restrict__ in, const float* __restrict__ w,
                          const float* __restrict__ b, __half* __restrict__ oh) {
    __shared__ float2 red[256];
    int row = blockIdx.x;
    const float* x = in + (size_t)row * Hdim;
    float s = 0.f, ss = 0.f;
    for (int i = threadIdx.x * 2; i < Hdim; i += 512) {
        float2 v = *(const float2*)(x + i);
        s += v.x + v.y;
        ss = fmaf(v.x, v.x, fmaf(v.y, v.y, ss));
    }
    red[threadIdx.x] = make_float2(s, ss);
    __syncthreads();
    for (int o = 128; o > 0; o >>= 1) {
        if (threadIdx.x < o) {
            float2 a = red[threadIdx.x], c = red[threadIdx.x + o];
            red[threadIdx.x] = make_float2(a.x + c.x, a.y + c.y);
        }
        __syncthreads();
    }
    float mean = red[0].x * (1.0f / Hdim);
    float var  = red[0].y * (1.0f / Hdim) - mean * mean;
    float rstd = rsqrtf(var + 1e-5f);
    for (int i = threadIdx.x * 2; i < Hdim; i += 512) {
        float2 v = *(const float2*)(x + i);
        float2 wv = *(const float2*)(w + i);
        float2 bv = *(const float2*)(b + i);
        float o0 = (v.x - mean) * rstd * wv.x + bv.x;
        float o1 = (v.y - mean) * rstd * wv.y + bv.y;
        *(__half2*)(oh + (size_t)row * Hdim + i) = __floats2half2_rn(o0, o1);
    }
}

// ============================ RoPE table (double precision trig) ============================
__global__ void rope_table_kernel() {
    int idx = blockIdx.x * blockDim.x + threadIdx.x;
    if (idx >= Sdim * 64) return;
    int s = idx >> 6, i = idx & 63;
    double invf = exp(-(double)i * (9.210340371976184 / 64.0)); // ln(10000)/64
    double th = (double)s * invf;
    g_cos[idx] = (float)cos(th);
    g_sin[idx] = (float)sin(th);
}

// ============================ QKV split + RoPE (half in, half out) ============================
__global__ void rope_kernel() {
    int row = blockIdx.x;      // b*S + s
    int h = blockIdx.y;
    int d = threadIdx.x;       // 0..127
    int s = row & (Sdim - 1);
    int b = row >> 11;
    const __half* src = g_qkvh + (size_t)row * (3 * Hdim) + h * (3 * Ddim);
    float q = __half2float(src[d]);
    float k = __half2float(src[Ddim + d]);
    __half v = src[2 * Ddim + d];
    int di = d & 63;
    float cs = g_cos[s * 64 + di];
    float sn = g_sin[s * 64 + di];
    float qp, kp;
    if (d < 64) { qp = -__half2float(src[d + 64]);      kp = -__half2float(src[Ddim + d + 64]); }
    else        { qp =  __half2float(src[d - 64]);      kp =  __half2float(src[Ddim + d - 64]); }
    size_t oidx = ((size_t)(b * NHdim + h) * Sdim + s) * Ddim + d;
    g_qh[oidx] = __float2half(q * cs + qp * sn);
    g_kh[oidx] = __float2half(k * cs + kp * sn);
    g_vh[oidx] = v;
}

// ============================ V transpose: [bh,S,D] -> [bh,D,S] ============================
__global__ void vt_kernel() {
    __shared__ __half tile[64][66];
    int bh = blockIdx.z;
    int s0 = blockIdx.x * 64, d0 = blockIdx.y * 64;
    const __half* src = g_vh + ((size_t)bh * Sdim + s0) * Ddim + d0;
#pragma unroll
    for (int i = 0; i < 16; i++) {
        int idx = threadIdx.x + i * 256;
        int r = idx >> 6, c = idx & 63;
        tile[r][c] = src[(size_t)r * Ddim + c];
    }
    __syncthreads();
    __half* dst = g_vt + ((size_t)bh * Ddim + d0) * Sdim + s0;
#pragma unroll
    for (int i = 0; i < 16; i++) {
        int idx = threadIdx.x + i * 256;
        int dr = idx >> 6, sc = idx & 63;
        dst[(size_t)dr * Sdim + sc] = tile[sc][dr];
    }
}

// ============================ HMMA flash attention (causal) ============================
// Br=128, Bc=32, 8 warps. Q frags register-resident; P frags built from S accums.
#define AT_SMEM (32768 + 2*16384)

__global__ void __launch_bounds__(256, 1) attn_kernel() {
    extern __shared__ char sm[];
    uint32_t smb = smem_u32(sm);
    uint32_t qbase = smb;
    int tid = threadIdx.x;
    int lane = tid & 31, wid = tid >> 5;
    int qt = gridDim.x - 1 - blockIdx.x;
    int bh = blockIdx.y;

    const __half* Qg  = g_qh + ((size_t)bh * Sdim + (size_t)qt * 128) * Ddim;
    const __half* Kg  = g_kh + (size_t)bh * Sdim * Ddim;
    const __half* VTg = g_vt + (size_t)bh * Ddim * Sdim;

    // ---- Q load (8 cp16/thread): row tid/2, kb pair (tid&1)*2 ----
    {
        int row = tid >> 1, kb0 = (tid & 1) * 2;
#pragma unroll
        for (int i = 0; i < 8; i++) {
            int kb = kb0 + (i >> 2), ch = i & 3;
            cp16(qbase + kb * 8192 + swoff(row, ch), Qg + (size_t)row * 128 + kb * 32 + ch * 8);
        }
    }
    auto load_stage = [&](int kt) {
        uint32_t st = smb + 32768 + (uint32_t)(kt & 1) * 16384;
        const __half* kp = Kg + (size_t)kt * 32 * 128;
#pragma unroll
        for (int i = 0; i < 2; i++) {
            int idx = tid + i * 256;
            int krow = idx >> 4, kb = (idx >> 2) & 3, ch = idx & 3;
            cp16(st + kb * 2048 + swoff(krow, ch), kp + (size_t)krow * 128 + kb * 32 + ch * 8);
        }
        const __half* vp = VTg + (size_t)kt * 32;
#pragma unroll
        for (int i = 0; i < 2; i++) {
            int idx = tid + i * 256;
            int drow = idx >> 2, ch = idx & 3;
            cp16(st + 8192 + swoff(drow, ch), vp + (size_t)drow * Sdim + ch * 8);
        }
    };

    int nkt = 4 * qt + 4;
    load_stage(0); CP_COMMIT();          // group0 = Q + stage0
    load_stage(1); CP_COMMIT();          // group1 = stage1
    CP_WAIT(1);
    __syncthreads();

    int mat = lane >> 3, mr = lane & 7;
    int fr_row = (mat & 1) * 8 + mr, fr_ch = mat >> 1;
    int wm = wid * 16;
    int tr = lane >> 2, tq = lane & 3;

    // Q fragments (held in registers for whole kernel)
    uint32_t qf[8][4];
#pragma unroll
    for (int kk = 0; kk < 8; kk++)
        ldsm4(qf[kk], qbase + (kk >> 1) * 8192 + swoff(wm + fr_row, (kk & 1) * 2 + fr_ch));

    float o_acc[16][4];
#pragma unroll
    for (int j = 0; j < 16; j++)
#pragma unroll
        for (int q = 0; q < 4; q++) o_acc[j][q] = 0.f;
    float m_run[2] = { -INFINITY, -INFINITY };
    float l_run[2] = { 0.f, 0.f };

    const float SC = 0.08838834764831845f * 1.4426950408889634f;  // scale * log2(e)
    int rowg0 = qt * 128 + wm + tr;

    for (int kt = 0; kt < nkt; kt++) {
        if (kt > 0) { CP_WAIT(1); __syncthreads(); }
        uint32_t st = smb + 32768 + (uint32_t)(kt & 1) * 16384;

        // ---- S = Q K^T ----
        float s_acc[4][4];
#pragma unroll
        for (int j = 0; j < 4; j++)
#pragma unroll
            for (int q = 0; q < 4; q++) s_acc[j][q] = 0.f;
#pragma unroll
        for (int kk = 0; kk < 8; kk++) {
            uint32_t kf[2][4];
#pragma unroll
            for (int g = 0; g < 2; g++)
                ldsm4(kf[g], st + (kk >> 1) * 2048 + swoff(16 * g + fr_row, (kk & 1) * 2 + fr_ch));
#pragma unroll
            for (int g = 0; g < 2; g++)
#pragma unroll
                for (int h = 0; h < 2; h++)
                    mma16816(s_acc[2 * g + h], qf[kk], kf[g][h], kf[g][h + 2]);
        }

        // ---- online softmax (units: scaled-logit * log2e) ----
        float v[4][4];
#pragma unroll
        for (int j = 0; j < 4; j++)
#pragma unroll
            for (int q = 0; q < 4; q++) {
                int colg = kt * 32 + j * 8 + tq * 2 + (q & 1);
                int rowg = rowg0 + (q >> 1) * 8;
                float x = s_acc[j][q] * SC;
                v[j][q] = (colg <= rowg) ? x : -1e30f;
            }
        float mrow0 = -1e30f, mrow1 = -1e30f;
#pragma unroll
        for (int j = 0; j < 4; j++) {
            mrow0 = fmaxf(mrow0, fmaxf(v[j][0], v[j][1]));
            mrow1 = fmaxf(mrow1, fmaxf(v[j][2], v[j][3]));
        }
        mrow0 = fmaxf(mrow0, __shfl_xor_sync(0xFFFFFFFF, mrow0, 1));
        mrow0 = fmaxf(mrow0, __shfl_xor_sync(0xFFFFFFFF, mrow0, 2));
        mrow1 = fmaxf(mrow1, __shfl_xor_sync(0xFFFFFFFF, mrow1, 1));
        mrow1 = fmaxf(mrow1, __shfl_xor_sync(0xFFFFFFFF, mrow1, 2));
        float mnew0 = fmaxf(m_run[0], mrow0);
        float mnew1 = fmaxf(m_run[1], mrow1);
        float alpha0 = ex2(m_run[0] - mnew0);
        float alpha1 = ex2(m_run[1] - mnew1);
        float p[4][4];
        float rs0 = 0.f, rs1 = 0.f;
#pragma unroll
        for (int j = 0; j < 4; j++) {
            p[j][0] = ex2(v[j][0] - mnew0); p[j][1] = ex2(v[j][1] - mnew0);
            p[j][2] = ex2(v[j][2] - mnew1); p[j][3] = ex2(v[j][3] - mnew1);
            rs0 += p[j][0] + p[j][1];
            rs1 += p[j][2] + p[j][3];
        }
        rs0 += __shfl_xor_sync(0xFFFFFFFF, rs0, 1);
        rs0 += __shfl_xor_sync(0xFFFFFFFF, rs0, 2);
        rs1 += __shfl_xor_sync(0xFFFFFFFF, rs1, 1);
        rs1 += __shfl_xor_sync(0xFFFFFFFF, rs1, 2);
        l_run[0] = l_run[0] * alpha0 + rs0;
        l_run[1] = l_run[1] * alpha1 + rs1;
        m_run[0] = mnew0;
        m_run[1] = mnew1;
#pragma unroll
        for (int jj = 0; jj < 16; jj++) {
            o_acc[jj][0] *= alpha0; o_acc[jj][1] *= alpha0;
            o_acc[jj][2] *= alpha1; o_acc[jj][3] *= alpha1;
        }

        // ---- P fragments (A-operand of PV) from S accumulators ----
        uint32_t pa[2][4];
#pragma unroll
        for (int t = 0; t < 2; t++) {
            pa[t][0] = f22u(p[2*t][0],   p[2*t][1]);
            pa[t][1] = f22u(p[2*t][2],   p[2*t][3]);
            pa[t][2] = f22u(p[2*t+1][0], p[2*t+1][1]);
            pa[t][3] = f22u(p[2*t+1][2], p[2*t+1][3]);
        }

        // ---- O += P V ----
#pragma unroll
        for (int g = 0; g < 8; g++) {
#pragma unroll
            for (int t = 0; t < 2; t++) {
                uint32_t vb[4];
                ldsm4(vb, st + 8192 + swoff(16 * g + fr_row, t * 2 + fr_ch));
                mma16816(o_acc[2 * g + 0], pa[t], vb[0], vb[2]);
                mma16816(o_acc[2 * g + 1], pa[t], vb[1], vb[3]);
            }
        }

        if (kt + 2 < nkt) {
            __syncthreads();
            load_stage(kt + 2);
            CP_COMMIT();
        }
    }

    // ---- epilogue: normalize and write ctx fp16 [B,S,H] ----
    float inv0 = 1.0f / l_run[0];
    float inv1 = 1.0f / l_run[1];
    int b = bh >> 4, h = bh & 15;
    int sg0 = qt * 128 + wm + tr;
#pragma unroll
    for (int jj = 0; jj < 16; jj++) {
        int dcol = jj * 8 + tq * 2;
        size_t a0 = ((size_t)(b * Sdim + sg0)) * Hdim + h * 128 + dcol;
        size_t a1 = ((size_t)(b * Sdim + sg0 + 8)) * Hdim + h * 128 + dcol;
        *(__half2*)(g_ctxh + a0) = __floats2half2_rn(o_acc[jj][0] * inv0, o_acc[jj][1] * inv0);
        *(__half2*)(g_ctxh + a1) = __floats2half2_rn(o_acc[jj][2] * inv1, o_acc[jj][3] * inv1);
    }
}

// ============================ mask passthrough ============================
__global__ void mask_kernel(const unsigned char* __restrict__ m, float* __restrict__ o, int n) {
    int i = blockIdx.x * blockDim.x + threadIdx.x;
    if (i < n) o[i] = m[i] ? 1.0f : 0.0f;
}

// ============================ launch ============================
extern "C" void kernel_launch(void* const* d_in, const int* in_sizes, int n_in,
                              void* d_out, int out_size) {
    const float* hs            = (const float*)d_in[0];
    const unsigned char* mask  = (const unsigned char*)d_in[1];
    const float* ln1w          = (const float*)d_in[2];
    const float* ln1b          = (const float*)d_in[3];
    const float* wqkv          = (const float*)d_in[4];
    const float* bqkv          = (const float*)d_in[5];
    const float* wdense        = (const float*)d_in[6];
    const float* bdense        = (const float*)d_in[7];
    const float* ln2w          = (const float*)d_in[8];
    const float* ln2b          = (const float*)d_in[9];
    const float* w1            = (const float*)d_in[10];
    const float* b1            = (const float*)d_in[11];
    const float* w2            = (const float*)d_in[12];
    const float* b2            = (const float*)d_in[13];
    float* out = (float*)d_out;

    float *phid;
    __half *pxh, *pctxh, *pinterh, *pqkvh, *pwqkvh, *pwdh, *pw1h, *pw2h;
    cudaGetSymbolAddress((void**)&phid,   g_hidden);
    cudaGetSymbolAddress((void**)&pxh,    g_xh);
    cudaGetSymbolAddress((void**)&pctxh,  g_ctxh);
    cudaGetSymbolAddress((void**)&pinterh, g_interh);
    cudaGetSymbolAddress((void**)&pqkvh,  g_qkvh);
    cudaGetSymbolAddress((void**)&pwqkvh, g_wqkvh);
    cudaGetSymbolAddress((void**)&pwdh,   g_wdh);
    cudaGetSymbolAddress((void**)&pw1h,   g_w1h);
    cudaGetSymbolAddress((void**)&pw2h,   g_w2h);

    cudaFuncSetAttribute(attn_kernel, cudaFuncAttributeMaxDynamicSharedMemorySize, AT_SMEM);
    cudaFuncSetAttribute(hgemm<1>, cudaFuncAttributeMaxDynamicSharedMemorySize, HM_SMEM);
    cudaFuncSetAttribute(hgemm<2>, cudaFuncAttributeMaxDynamicSharedMemorySize, HM_SMEM);
    cudaFuncSetAttribute(hgemm<3>, cudaFuncAttributeMaxDynamicSharedMemorySize, HM_SMEM);

    // weight prep: fp32 -> fp16
    cvt_kernel<<<(3*Hdim*Hdim/2 + 255)/256, 256>>>(wqkv, pwqkvh, 3*Hdim*Hdim/2);
    cvt_kernel<<<(Hdim*Hdim/2   + 255)/256, 256>>>(wdense, pwdh, Hdim*Hdim/2);
    cvt_kernel<<<(FFdim*Hdim/2  + 255)/256, 256>>>(w1,     pw1h, FFdim*Hdim/2);
    cvt_kernel<<<(Hdim*FFdim/2  + 255)/256, 256>>>(w2,     pw2h, Hdim*FFdim/2);
    // LN1 -> xh
    ln_kernel<<<Mrows, 256>>>(hs, ln1w, ln1b, pxh);
    // RoPE trig table
    rope_table_kernel<<<(Sdim * 64) / 256, 256>>>();
    // QKV = x @ wqkv^T + bqkv (half out)
    hgemm<3><<<dim3(3 * Hdim / GBN, Mrows / GBM), 512, HM_SMEM>>>(
        pxh, pwqkvh, bqkv, nullptr, nullptr, pqkvh, Mrows, 3 * Hdim, Hdim);
    // split + rope -> qh/kh/vh (half, [B,NH,S,D])
    rope_kernel<<<dim3(Mrows, NHdim), 128>>>();
    // V transpose -> vt (half, [B,NH,D,S])
    vt_kernel<<<dim3(Sdim / 64, Ddim / 64, Bdim * NHdim), 256>>>();
    // HMMA flash attention -> ctxh
    attn_kernel<<<dim3(Sdim / 128, Bdim * NHdim), 256, AT_SMEM>>>();
    // dense + residual(hidden_states) -> g_hidden (fp32)
    hgemm<2><<<dim3(Hdim / GBN, Mrows / GBM), 512, HM_SMEM>>>(
        pctxh, pwdh, bdense, hs, phid, nullptr, Mrows, Hdim, Hdim);
    // LN2 -> xh
    ln_kernel<<<Mrows, 256>>>(phid, ln2w, ln2b, pxh);
    // FF1 + GELU -> interh (fp16)
    hgemm<1><<<dim3(FFdim / GBN, Mrows / GBM), 512, HM_SMEM>>>(
        pxh, pw1h, b1, nullptr, nullptr, pinterh, Mrows, FFdim, Hdim);
    // FF2 + residual(g_hidden) -> out
    hgemm<2><<<dim3(Hdim / GBN, Mrows / GBM), 512, HM_SMEM>>>(
        pinterh, pw2h, b2, phid, out, nullptr, Mrows, Hdim, FFdim);
    // if output also carries the attention mask, convert it after hidden
    long long hid_elems = (long long)Mrows * Hdim;           // 8388608
    long long mask_elems = (long long)Sdim * Sdim;           // 4194304
    if ((long long)out_size >= hid_elems + mask_elems) {
        mask_kernel<<<(int)(mask_elems / 256), 256>>>(mask, out + hid_elems, (int)mask_elems);
    }
}